// round 4
// baseline (speedup 1.0000x reference)
#include <cuda_runtime.h>
#include <cuda_bf16.h>
#include <math.h>

#define B 64
#define NP 32
#define NS 72
#define HD 256
#define H 4
#define F 64
#define CSE 112
#define L 4
#define NC 110
#define EPS 1e-6f

// ---------------- device scratch (no allocations allowed) ----------------
// NOTE: these symbols are ONLY referenced from device code. Referencing them
// from host code yields the host shadow address, which on ATS-coherent GB300
// is silently readable/writable by the GPU -> wrong results with no fault.
__device__ float g_g [B*HD];        // context gate (B,HD)
__device__ float g_c [B*HD];        // per-layer g@cp_W + cp_b
__device__ float g_x [B*NS*HD];     // residual stream
__device__ float g_h [B*NS*HD];     // LN(x)+ctx
__device__ float g_hl[B*NS*HD];
__device__ float g_hr[B*NS*HD];
__device__ float g_hg[B*NS*HD];     // gat output
__device__ float g_ge[B*HD];        // mean-pooled

// ---------------- block LN statistics over 256 threads ----------------
__device__ __forceinline__ void block_stats256(float val, float& mean, float& rstd) {
    float s = val, sq = val * val;
    #pragma unroll
    for (int o = 16; o; o >>= 1) {
        s  += __shfl_xor_sync(0xffffffffu, s,  o);
        sq += __shfl_xor_sync(0xffffffffu, sq, o);
    }
    __shared__ float ss[8], sqq[8];
    int lane = threadIdx.x & 31, w = threadIdx.x >> 5;
    if (lane == 0) { ss[w] = s; sqq[w] = sq; }
    __syncthreads();
    if (w == 0) {
        s  = (lane < 8) ? ss[lane]  : 0.f;
        sq = (lane < 8) ? sqq[lane] : 0.f;
        #pragma unroll
        for (int o = 4; o; o >>= 1) {
            s  += __shfl_xor_sync(0xffffffffu, s,  o);
            sq += __shfl_xor_sync(0xffffffffu, sq, o);
        }
        if (lane == 0) { ss[0] = s; sqq[0] = sq; }
    }
    __syncthreads();
    s = ss[0]; sq = sqq[0];
    mean = s * (1.f / 256.f);
    float var = sq * (1.f / 256.f) - mean * mean;
    rstd = rsqrtf(var + EPS);
}

// ---------------- context MLP: g = relu(LN(ctx @ ctx_W + ctx_b)) ----------------
__global__ void ctx_kernel(const float* __restrict__ cc, const float* __restrict__ W,
                           const float* __restrict__ bias, const float* __restrict__ lns,
                           const float* __restrict__ lnb) {
    int b = blockIdx.x, d = threadIdx.x;
    __shared__ float cs[CSE];
    if (d < CSE) cs[d] = cc[b*CSE + d];
    __syncthreads();
    float acc = bias[d];
    #pragma unroll 4
    for (int k = 0; k < CSE; k++) acc += cs[k] * W[k*HD + d];
    float mean, rstd;
    block_stats256(acc, mean, rstd);
    float y = (acc - mean) * rstd * lns[d] + lnb[d];
    g_g[b*HD + d] = fmaxf(y, 0.f);
}

// ---------------- input embed: x[b,s,d] = sum_p obs[b,p,s]*in_W[p,d] + in_b[d] ----------------
__global__ void embed_kernel(const float* __restrict__ so, const float* __restrict__ W,
                             const float* __restrict__ bias) {
    int bs = blockIdx.x; int b = bs / NS, s = bs % NS; int d = threadIdx.x;
    __shared__ float sv[NP];
    if (d < NP) sv[d] = so[(b*NP + d)*NS + s];
    __syncthreads();
    float acc = bias[d];
    #pragma unroll
    for (int p = 0; p < NP; p++) acc += sv[p] * W[p*HD + d];
    g_x[bs*HD + d] = acc;
}

// ---------------- c[b,:] = g[b] @ cp_W[l] + cp_b[l] ----------------
__global__ void cp_kernel(const float* __restrict__ W, const float* __restrict__ bias) {
    int b = blockIdx.x, d = threadIdx.x;
    __shared__ float gs[HD];
    gs[d] = g_g[b*HD + d];
    __syncthreads();
    float acc = bias[d];
    #pragma unroll 8
    for (int k = 0; k < HD; k++) acc += gs[k] * W[k*HD + d];
    g_c[b*HD + d] = acc;
}

// ---------------- h = LN(x)*s+b + c ----------------
__global__ void ln_add_kernel(const float* __restrict__ lns, const float* __restrict__ lnb) {
    int bs = blockIdx.x, d = threadIdx.x; int b = bs / NS;
    float val = g_x[bs*HD + d];
    float mean, rstd;
    block_stats256(val, mean, rstd);
    g_h[bs*HD + d] = (val - mean) * rstd * lns[d] + lnb[d] + g_c[b*HD + d];
}

// ---------------- tiled fp32 GEMM: C[M,256] (+)= A[M,256] @ W[256,256] (+ bias) ----------------
// MODE 0: A=g_h,  C=g_hl, no bias, overwrite
// MODE 1: A=g_h,  C=g_hr, no bias, overwrite
// MODE 2: A=g_hg, C=g_x,  bias,    accumulate
// Scratch buffers are resolved IN DEVICE CODE (true device addresses).
template<int MODE>
__global__ void gemm256_kernel(const float* __restrict__ W, const float* __restrict__ bias) {
    const float* A = (MODE == 2) ? g_hg : g_h;
    float*       C = (MODE == 0) ? g_hl : (MODE == 1) ? g_hr : g_x;
    __shared__ float As[16][64];
    __shared__ float Ws[16][64];
    int tid = threadIdx.x;
    int row0 = blockIdx.x * 64;
    int n0   = blockIdx.y * 64;
    int tx = tid % 16, ty = tid / 16;
    int am = tid / 4, ak4 = tid % 4;
    int wk = tid / 16, wn4 = tid % 16;
    float acc[4][4] = {};
    for (int k0 = 0; k0 < 256; k0 += 16) {
        float4 av = *(const float4*)&A[(row0 + am)*256 + k0 + ak4*4];
        As[ak4*4 + 0][am] = av.x;
        As[ak4*4 + 1][am] = av.y;
        As[ak4*4 + 2][am] = av.z;
        As[ak4*4 + 3][am] = av.w;
        *(float4*)&Ws[wk][wn4*4] = *(const float4*)&W[(k0 + wk)*256 + n0 + wn4*4];
        __syncthreads();
        #pragma unroll
        for (int k = 0; k < 16; k++) {
            float4 a = *(const float4*)&As[k][ty*4];
            float4 w = *(const float4*)&Ws[k][tx*4];
            float ar[4] = {a.x, a.y, a.z, a.w};
            float wr[4] = {w.x, w.y, w.z, w.w};
            #pragma unroll
            for (int i = 0; i < 4; i++)
                #pragma unroll
                for (int j = 0; j < 4; j++)
                    acc[i][j] += ar[i] * wr[j];
        }
        __syncthreads();
    }
    #pragma unroll
    for (int i = 0; i < 4; i++) {
        int r = row0 + ty*4 + i;
        #pragma unroll
        for (int j = 0; j < 4; j++) {
            int cn = n0 + tx*4 + j;
            float v = acc[i][j];
            if (MODE == 2) v += bias[cn];
            if (MODE == 2) C[r*256 + cn] += v;
            else           C[r*256 + cn] = v;
        }
    }
}

// ---------------- GATv2 attention, one block per batch ----------------
// smem: hl(72*256) + hr(72*256) + sc(288) + at(288) floats
#define ATTN_SMEM ((2*NS*HD + 2*NS*H) * sizeof(float))
__global__ void attn_kernel(const float* __restrict__ adj, const float* __restrict__ Wa) {
    int b = blockIdx.x;
    int tid = threadIdx.x, lane = tid & 31, warp = tid >> 5;
    extern __shared__ float sm[];
    float* hls = sm;
    float* hrs = sm + NS*HD;
    float* sc  = sm + 2*NS*HD;
    float* at  = sc + NS*H;
    __shared__ float wa_s[H*F];
    wa_s[tid] = Wa[tid];
    const float* src_l = g_hl + b*NS*HD;
    const float* src_r = g_hr + b*NS*HD;
    for (int i = tid; i < NS*HD; i += 256) { hls[i] = src_l[i]; hrs[i] = src_r[i]; }
    __syncthreads();

    for (int i = 0; i < NS; i++) {
        // scores for all (j,h): 288 entries, warp-per-entry, lanes reduce over f
        for (int e = warp; e < NS*H; e += 8) {
            int j = e >> 2, h = e & 3;
            float p = 0.f;
            #pragma unroll
            for (int fc = 0; fc < F; fc += 32) {
                int f = fc + lane;
                float v = hls[i*HD + h*F + f] + hrs[j*HD + h*F + f];
                v = (v > 0.f) ? v : 0.2f * v;
                p += wa_s[h*F + f] * v;
            }
            #pragma unroll
            for (int o = 16; o; o >>= 1) p += __shfl_xor_sync(0xffffffffu, p, o);
            if (lane == 0) sc[e] = (adj[i*NS + j] > 0.f) ? p : -1e9f;
        }
        __syncthreads();
        // softmax over j, one warp per head
        if (warp < H) {
            int h = warp;
            float m = -1e30f;
            for (int j = lane; j < NS; j += 32) m = fmaxf(m, sc[j*H + h]);
            #pragma unroll
            for (int o = 16; o; o >>= 1) m = fmaxf(m, __shfl_xor_sync(0xffffffffu, m, o));
            float s = 0.f;
            for (int j = lane; j < NS; j += 32) { float e2 = expf(sc[j*H + h] - m); at[j*H + h] = e2; s += e2; }
            #pragma unroll
            for (int o = 16; o; o >>= 1) s += __shfl_xor_sync(0xffffffffu, s, o);
            float inv = 1.f / s;
            for (int j = lane; j < NS; j += 32) at[j*H + h] *= inv;
        }
        __syncthreads();
        // out[i, d] = sum_j at[j,h] * hr[j, d]   (d = h*64+f)
        float acc = 0.f;
        int h = tid >> 6;
        #pragma unroll 8
        for (int j = 0; j < NS; j++) acc += at[j*H + h] * hrs[j*HD + tid];
        g_hg[(b*NS + i)*HD + tid] = acc;
        __syncthreads();
    }
}

// ---------------- mean pool over NS ----------------
__global__ void mean_kernel() {
    int b = blockIdx.x, d = threadIdx.x;
    float acc = 0.f;
    #pragma unroll 8
    for (int s = 0; s < NS; s++) acc += g_x[(b*NS + s)*HD + d];
    g_ge[b*HD + d] = acc * (1.f / (float)NS);
}

// ---------------- output heads ----------------
#define OUT_CARD 0
#define OUT_AT   (B*NC)                 // 7040
#define OUT_SRC  (OUT_AT + B*3)         // 7232
#define OUT_TGT  (OUT_SRC + B*NS)       // 11840
#define OUT_VAL  (OUT_TGT + B*NS)       // 16448
__global__ void heads_kernel(const float* __restrict__ cW, const float* __restrict__ cb,
                             const float* __restrict__ aW, const float* __restrict__ ab,
                             const float* __restrict__ sW, const float* __restrict__ sb,
                             const float* __restrict__ tW, const float* __restrict__ tb,
                             const float* __restrict__ v1W, const float* __restrict__ v1b,
                             const float* __restrict__ v2W, const float* __restrict__ v2b,
                             float* __restrict__ out) {
    int b = blockIdx.x, tid = threadIdx.x;
    __shared__ float ge[HD];
    __shared__ float vh[128];
    __shared__ float vpart[4];
    ge[tid] = g_ge[b*HD + tid];
    __syncthreads();
    if (tid < NC) {
        float a = cb[tid];
        for (int k = 0; k < HD; k++) a += ge[k] * cW[k*NC + tid];
        out[OUT_CARD + b*NC + tid] = a;
    }
    if (tid < 3) {
        float a = ab[tid];
        for (int k = 0; k < HD; k++) a += ge[k] * aW[k*3 + tid];
        out[OUT_AT + b*3 + tid] = a;
    }
    if (tid < NS) {
        float a = sb[tid], t = tb[tid];
        for (int k = 0; k < HD; k++) { a += ge[k] * sW[k*NS + tid]; t += ge[k] * tW[k*NS + tid]; }
        out[OUT_SRC + b*NS + tid] = a;
        out[OUT_TGT + b*NS + tid] = t;
    }
    if (tid < 128) {
        float a = v1b[tid];
        for (int k = 0; k < HD; k++) a += ge[k] * v1W[k*128 + tid];
        vh[tid] = fmaxf(a, 0.f);
    }
    __syncthreads();
    if (tid < 128) {
        float p = vh[tid] * v2W[tid];
        #pragma unroll
        for (int o = 16; o; o >>= 1) p += __shfl_xor_sync(0xffffffffu, p, o);
        if ((tid & 31) == 0) vpart[tid >> 5] = p;
    }
    __syncthreads();
    if (tid == 0) {
        float s = vpart[0] + vpart[1] + vpart[2] + vpart[3] + v2b[0];
        out[OUT_VAL + b] = tanhf(s);
    }
}

// ---------------- launch ----------------
extern "C" void kernel_launch(void* const* d_in, const int* in_sizes, int n_in,
                              void* d_out, int out_size) {
    const float* spatial_obs = (const float*)d_in[0];
    const float* card_ctx    = (const float*)d_in[1];
    const float* adj         = (const float*)d_in[2];
    const float* ctx_W  = (const float*)d_in[3];
    const float* ctx_b  = (const float*)d_in[4];
    const float* lnc_s  = (const float*)d_in[5];
    const float* lnc_b  = (const float*)d_in[6];
    const float* in_W   = (const float*)d_in[7];
    const float* in_b   = (const float*)d_in[8];
    const float* lnp_s  = (const float*)d_in[9];
    const float* lnp_b  = (const float*)d_in[10];
    const float* cp_W   = (const float*)d_in[11];
    const float* cp_b   = (const float*)d_in[12];
    const float* Wl     = (const float*)d_in[13];
    const float* Wr     = (const float*)d_in[14];
    const float* Wa     = (const float*)d_in[15];
    const float* op_W   = (const float*)d_in[16];
    const float* op_b   = (const float*)d_in[17];
    const float* card_W = (const float*)d_in[18];
    const float* card_b = (const float*)d_in[19];
    const float* at_W   = (const float*)d_in[20];
    const float* at_b   = (const float*)d_in[21];
    const float* src_W  = (const float*)d_in[22];
    const float* src_b  = (const float*)d_in[23];
    const float* tgt_W  = (const float*)d_in[24];
    const float* tgt_b  = (const float*)d_in[25];
    const float* v1_W   = (const float*)d_in[26];
    const float* v1_b   = (const float*)d_in[27];
    const float* v2_W   = (const float*)d_in[28];
    const float* v2_b   = (const float*)d_in[29];
    float* out = (float*)d_out;

    static bool attr_done = false;
    if (!attr_done) {
        cudaFuncSetAttribute(attn_kernel, cudaFuncAttributeMaxDynamicSharedMemorySize, ATTN_SMEM);
        attr_done = true;
    }

    ctx_kernel<<<B, HD>>>(card_ctx, ctx_W, ctx_b, lnc_s, lnc_b);
    embed_kernel<<<B*NS, HD>>>(spatial_obs, in_W, in_b);

    dim3 ggrid(B*NS/64, HD/64);
    for (int l = 0; l < L; l++) {
        cp_kernel<<<B, HD>>>(cp_W + l*HD*HD, cp_b + l*HD);
        ln_add_kernel<<<B*NS, HD>>>(lnp_s + l*HD, lnp_b + l*HD);
        gemm256_kernel<0><<<ggrid, 256>>>(Wl + l*HD*HD, nullptr);
        gemm256_kernel<1><<<ggrid, 256>>>(Wr + l*HD*HD, nullptr);
        attn_kernel<<<B, 256, ATTN_SMEM>>>(adj, Wa + l*H*F);
        gemm256_kernel<2><<<ggrid, 256>>>(op_W + l*HD*HD, op_b + l*HD);
    }

    mean_kernel<<<B, HD>>>();
    heads_kernel<<<B, HD>>>(card_W, card_b, at_W, at_b, src_W, src_b,
                            tgt_W, tgt_b, v1_W, v1_b, v2_W, v2_b, out);
}

// round 5
// speedup vs baseline: 2.6343x; 2.6343x over previous
#include <cuda_runtime.h>
#include <cuda_bf16.h>
#include <math.h>

#define B 64
#define NP 32
#define NS 72
#define HD 256
#define H 4
#define F 64
#define CSE 112
#define L 4
#define NC 110
#define EPS 1e-6f

// ---------------- device scratch (no allocations allowed) ----------------
// NOTE: these symbols are ONLY referenced from device code. Host-side symbol
// references give the host shadow address (ATS-coherent GB300 -> silent wrong).
__device__ float g_g [B*HD];
__device__ float g_c [B*HD];
__device__ float g_x [B*NS*HD];
__device__ float g_h [B*NS*HD];
__device__ float g_hl[B*NS*HD];
__device__ float g_hr[B*NS*HD];
__device__ float g_hg[B*NS*HD];
__device__ float g_ge[B*HD];

// ---------------- block LN statistics over 256 threads ----------------
__device__ __forceinline__ void block_stats256(float val, float& mean, float& rstd) {
    float s = val, sq = val * val;
    #pragma unroll
    for (int o = 16; o; o >>= 1) {
        s  += __shfl_xor_sync(0xffffffffu, s,  o);
        sq += __shfl_xor_sync(0xffffffffu, sq, o);
    }
    __shared__ float ss[8], sqq[8];
    int lane = threadIdx.x & 31, w = threadIdx.x >> 5;
    if (lane == 0) { ss[w] = s; sqq[w] = sq; }
    __syncthreads();
    if (w == 0) {
        s  = (lane < 8) ? ss[lane]  : 0.f;
        sq = (lane < 8) ? sqq[lane] : 0.f;
        #pragma unroll
        for (int o = 4; o; o >>= 1) {
            s  += __shfl_xor_sync(0xffffffffu, s,  o);
            sq += __shfl_xor_sync(0xffffffffu, sq, o);
        }
        if (lane == 0) { ss[0] = s; sqq[0] = sq; }
    }
    __syncthreads();
    s = ss[0]; sq = sqq[0];
    mean = s * (1.f / 256.f);
    float var = sq * (1.f / 256.f) - mean * mean;
    rstd = rsqrtf(var + EPS);
}

// ---------------- context MLP: g = relu(LN(ctx @ ctx_W + ctx_b)) ----------------
__global__ void ctx_kernel(const float* __restrict__ cc, const float* __restrict__ W,
                           const float* __restrict__ bias, const float* __restrict__ lns,
                           const float* __restrict__ lnb) {
    int b = blockIdx.x, d = threadIdx.x;
    __shared__ float cs[CSE];
    if (d < CSE) cs[d] = cc[b*CSE + d];
    __syncthreads();
    float acc = bias[d];
    #pragma unroll 4
    for (int k = 0; k < CSE; k++) acc += cs[k] * W[k*HD + d];
    float mean, rstd;
    block_stats256(acc, mean, rstd);
    float y = (acc - mean) * rstd * lns[d] + lnb[d];
    g_g[b*HD + d] = fmaxf(y, 0.f);
}

// ---------------- input embed ----------------
__global__ void embed_kernel(const float* __restrict__ so, const float* __restrict__ W,
                             const float* __restrict__ bias) {
    int bs = blockIdx.x; int b = bs / NS, s = bs % NS; int d = threadIdx.x;
    __shared__ float sv[NP];
    if (d < NP) sv[d] = so[(b*NP + d)*NS + s];
    __syncthreads();
    float acc = bias[d];
    #pragma unroll
    for (int p = 0; p < NP; p++) acc += sv[p] * W[p*HD + d];
    g_x[bs*HD + d] = acc;
}

// ---------------- c[b,:] = g[b] @ cp_W[l] + cp_b[l] ----------------
__global__ void cp_kernel(const float* __restrict__ W, const float* __restrict__ bias) {
    int b = blockIdx.x, d = threadIdx.x;
    __shared__ float gs[HD];
    gs[d] = g_g[b*HD + d];
    __syncthreads();
    float acc = bias[d];
    #pragma unroll 8
    for (int k = 0; k < HD; k++) acc += gs[k] * W[k*HD + d];
    g_c[b*HD + d] = acc;
}

// ---------------- h = LN(x)*s+b + c ----------------
__global__ void ln_add_kernel(const float* __restrict__ lns, const float* __restrict__ lnb) {
    int bs = blockIdx.x, d = threadIdx.x; int b = bs / NS;
    float val = g_x[bs*HD + d];
    float mean, rstd;
    block_stats256(val, mean, rstd);
    g_h[bs*HD + d] = (val - mean) * rstd * lns[d] + lnb[d] + g_c[b*HD + d];
}

// ---------------- tiled fp32 GEMM ----------------
// MODE 0: A=g_h,  C=g_hl  | MODE 1: A=g_h, C=g_hr | MODE 2: A=g_hg, C+=..., bias
template<int MODE>
__global__ void gemm256_kernel(const float* __restrict__ W, const float* __restrict__ bias) {
    const float* A = (MODE == 2) ? g_hg : g_h;
    float*       C = (MODE == 0) ? g_hl : (MODE == 1) ? g_hr : g_x;
    __shared__ float As[16][64];
    __shared__ float Ws[16][64];
    int tid = threadIdx.x;
    int row0 = blockIdx.x * 64;
    int n0   = blockIdx.y * 64;
    int tx = tid % 16, ty = tid / 16;
    int am = tid / 4, ak4 = tid % 4;
    int wk = tid / 16, wn4 = tid % 16;
    float acc[4][4] = {};
    for (int k0 = 0; k0 < 256; k0 += 16) {
        float4 av = *(const float4*)&A[(row0 + am)*256 + k0 + ak4*4];
        As[ak4*4 + 0][am] = av.x;
        As[ak4*4 + 1][am] = av.y;
        As[ak4*4 + 2][am] = av.z;
        As[ak4*4 + 3][am] = av.w;
        *(float4*)&Ws[wk][wn4*4] = *(const float4*)&W[(k0 + wk)*256 + n0 + wn4*4];
        __syncthreads();
        #pragma unroll
        for (int k = 0; k < 16; k++) {
            float4 a = *(const float4*)&As[k][ty*4];
            float4 w = *(const float4*)&Ws[k][tx*4];
            float ar[4] = {a.x, a.y, a.z, a.w};
            float wr[4] = {w.x, w.y, w.z, w.w};
            #pragma unroll
            for (int i = 0; i < 4; i++)
                #pragma unroll
                for (int j = 0; j < 4; j++)
                    acc[i][j] += ar[i] * wr[j];
        }
        __syncthreads();
    }
    #pragma unroll
    for (int i = 0; i < 4; i++) {
        int r = row0 + ty*4 + i;
        #pragma unroll
        for (int j = 0; j < 4; j++) {
            int cn = n0 + tx*4 + j;
            float v = acc[i][j];
            if (MODE == 2) v += bias[cn];
            if (MODE == 2) C[r*256 + cn] += v;
            else           C[r*256 + cn] = v;
        }
    }
}

// ---------------- GATv2 attention, parallel over (batch, i-chunk) ----------------
// grid (B, NS/TI), 256 threads. Each CTA computes TI target rows.
#define TI 8
#define ATTN_SMEM ((NS*HD + TI*HD + TI*NS*H + TI*NS) * sizeof(float))
__global__ void attn_kernel(const float* __restrict__ adj, const float* __restrict__ Wa) {
    int b = blockIdx.x;
    int i0 = blockIdx.y * TI;
    int tid = threadIdx.x, lane = tid & 31, warp = tid >> 5;
    extern __shared__ float sm[];
    float* hrs  = sm;                 // NS*HD
    float* hls  = hrs + NS*HD;        // TI*HD
    float* sc   = hls + TI*HD;        // TI*NS*H, layout [(i*NS+j)*H + h]
    float* adjr = sc + TI*NS*H;       // TI*NS
    __shared__ float wa_s[H*F];
    wa_s[tid] = Wa[tid];
    const float* src_r = g_hr + b*NS*HD;
    const float* src_l = g_hl + (b*NS + i0)*HD;
    for (int k = tid; k < NS*HD; k += 256) hrs[k] = src_r[k];
    for (int k = tid; k < TI*HD; k += 256) hls[k] = src_l[k];
    for (int k = tid; k < TI*NS; k += 256) adjr[k] = adj[(i0 + k/NS)*NS + (k % NS)];
    __syncthreads();

    // scores: TI*NS*H = 2304 entries, one warp per entry, lanes reduce over f
    for (int e = warp; e < TI*NS*H; e += 8) {
        int i = e / (NS*H);
        int rem = e - i*(NS*H);
        int j = rem / H, h = rem - j*H;
        float p = 0.f;
        #pragma unroll
        for (int fc = 0; fc < F; fc += 32) {
            int f = fc + lane;
            float v = hls[i*HD + h*F + f] + hrs[j*HD + h*F + f];
            v = (v > 0.f) ? v : 0.2f * v;
            p += wa_s[h*F + f] * v;
        }
        #pragma unroll
        for (int o = 16; o; o >>= 1) p += __shfl_xor_sync(0xffffffffu, p, o);
        if (lane == 0) sc[(i*NS + j)*H + h] = (adjr[i*NS + j] > 0.f) ? p : -1e9f;
    }
    __syncthreads();

    // softmax over j: TI*H = 32 (i,h) pairs, one warp per pair (4 rounds)
    for (int p = warp; p < TI*H; p += 8) {
        int i = p >> 2, h = p & 3;
        float m = -1e30f;
        for (int j = lane; j < NS; j += 32) m = fmaxf(m, sc[(i*NS + j)*H + h]);
        #pragma unroll
        for (int o = 16; o; o >>= 1) m = fmaxf(m, __shfl_xor_sync(0xffffffffu, m, o));
        float s = 0.f;
        for (int j = lane; j < NS; j += 32) {
            float e2 = expf(sc[(i*NS + j)*H + h] - m);
            sc[(i*NS + j)*H + h] = e2; s += e2;
        }
        #pragma unroll
        for (int o = 16; o; o >>= 1) s += __shfl_xor_sync(0xffffffffu, s, o);
        float inv = 1.f / s;
        for (int j = lane; j < NS; j += 32) sc[(i*NS + j)*H + h] *= inv;
    }
    __syncthreads();

    // output: thread owns column d; j outer (reuse hr[j][d] across TI rows)
    int d = tid, h = d >> 6;
    float acc[TI] = {};
    for (int j = 0; j < NS; j++) {
        float hv = hrs[j*HD + d];
        #pragma unroll
        for (int i = 0; i < TI; i++) acc[i] += sc[(i*NS + j)*H + h] * hv;
    }
    #pragma unroll
    for (int i = 0; i < TI; i++) g_hg[(b*NS + i0 + i)*HD + d] = acc[i];
}

// ---------------- mean pool over NS ----------------
__global__ void mean_kernel() {
    int b = blockIdx.x, d = threadIdx.x;
    float acc = 0.f;
    #pragma unroll 8
    for (int s = 0; s < NS; s++) acc += g_x[(b*NS + s)*HD + d];
    g_ge[b*HD + d] = acc * (1.f / (float)NS);
}

// ---------------- output heads ----------------
#define OUT_CARD 0
#define OUT_AT   (B*NC)
#define OUT_SRC  (OUT_AT + B*3)
#define OUT_TGT  (OUT_SRC + B*NS)
#define OUT_VAL  (OUT_TGT + B*NS)
__global__ void heads_kernel(const float* __restrict__ cW, const float* __restrict__ cb,
                             const float* __restrict__ aW, const float* __restrict__ ab,
                             const float* __restrict__ sW, const float* __restrict__ sb,
                             const float* __restrict__ tW, const float* __restrict__ tb,
                             const float* __restrict__ v1W, const float* __restrict__ v1b,
                             const float* __restrict__ v2W, const float* __restrict__ v2b,
                             float* __restrict__ out) {
    int b = blockIdx.x, tid = threadIdx.x;
    __shared__ float ge[HD];
    __shared__ float vh[128];
    __shared__ float vpart[4];
    ge[tid] = g_ge[b*HD + tid];
    __syncthreads();
    if (tid < NC) {
        float a = cb[tid];
        for (int k = 0; k < HD; k++) a += ge[k] * cW[k*NC + tid];
        out[OUT_CARD + b*NC + tid] = a;
    }
    if (tid < 3) {
        float a = ab[tid];
        for (int k = 0; k < HD; k++) a += ge[k] * aW[k*3 + tid];
        out[OUT_AT + b*3 + tid] = a;
    }
    if (tid < NS) {
        float a = sb[tid], t = tb[tid];
        for (int k = 0; k < HD; k++) { a += ge[k] * sW[k*NS + tid]; t += ge[k] * tW[k*NS + tid]; }
        out[OUT_SRC + b*NS + tid] = a;
        out[OUT_TGT + b*NS + tid] = t;
    }
    if (tid < 128) {
        float a = v1b[tid];
        for (int k = 0; k < HD; k++) a += ge[k] * v1W[k*128 + tid];
        vh[tid] = fmaxf(a, 0.f);
    }
    __syncthreads();
    if (tid < 128) {
        float p = vh[tid] * v2W[tid];
        #pragma unroll
        for (int o = 16; o; o >>= 1) p += __shfl_xor_sync(0xffffffffu, p, o);
        if ((tid & 31) == 0) vpart[tid >> 5] = p;
    }
    __syncthreads();
    if (tid == 0) {
        float s = vpart[0] + vpart[1] + vpart[2] + vpart[3] + v2b[0];
        out[OUT_VAL + b] = tanhf(s);
    }
}

// ---------------- launch ----------------
extern "C" void kernel_launch(void* const* d_in, const int* in_sizes, int n_in,
                              void* d_out, int out_size) {
    const float* spatial_obs = (const float*)d_in[0];
    const float* card_ctx    = (const float*)d_in[1];
    const float* adj         = (const float*)d_in[2];
    const float* ctx_W  = (const float*)d_in[3];
    const float* ctx_b  = (const float*)d_in[4];
    const float* lnc_s  = (const float*)d_in[5];
    const float* lnc_b  = (const float*)d_in[6];
    const float* in_W   = (const float*)d_in[7];
    const float* in_b   = (const float*)d_in[8];
    const float* lnp_s  = (const float*)d_in[9];
    const float* lnp_b  = (const float*)d_in[10];
    const float* cp_W   = (const float*)d_in[11];
    const float* cp_b   = (const float*)d_in[12];
    const float* Wl     = (const float*)d_in[13];
    const float* Wr     = (const float*)d_in[14];
    const float* Wa     = (const float*)d_in[15];
    const float* op_W   = (const float*)d_in[16];
    const float* op_b   = (const float*)d_in[17];
    const float* card_W = (const float*)d_in[18];
    const float* card_b = (const float*)d_in[19];
    const float* at_W   = (const float*)d_in[20];
    const float* at_b   = (const float*)d_in[21];
    const float* src_W  = (const float*)d_in[22];
    const float* src_b  = (const float*)d_in[23];
    const float* tgt_W  = (const float*)d_in[24];
    const float* tgt_b  = (const float*)d_in[25];
    const float* v1_W   = (const float*)d_in[26];
    const float* v1_b   = (const float*)d_in[27];
    const float* v2_W   = (const float*)d_in[28];
    const float* v2_b   = (const float*)d_in[29];
    float* out = (float*)d_out;

    cudaFuncSetAttribute(attn_kernel, cudaFuncAttributeMaxDynamicSharedMemorySize, ATTN_SMEM);

    ctx_kernel<<<B, HD>>>(card_ctx, ctx_W, ctx_b, lnc_s, lnc_b);
    embed_kernel<<<B*NS, HD>>>(spatial_obs, in_W, in_b);

    dim3 ggrid(B*NS/64, HD/64);
    dim3 agrid(B, NS/TI);
    for (int l = 0; l < L; l++) {
        cp_kernel<<<B, HD>>>(cp_W + l*HD*HD, cp_b + l*HD);
        ln_add_kernel<<<B*NS, HD>>>(lnp_s + l*HD, lnp_b + l*HD);
        gemm256_kernel<0><<<ggrid, 256>>>(Wl + l*HD*HD, nullptr);
        gemm256_kernel<1><<<ggrid, 256>>>(Wr + l*HD*HD, nullptr);
        attn_kernel<<<agrid, 256, ATTN_SMEM>>>(adj, Wa + l*H*F);
        gemm256_kernel<2><<<ggrid, 256>>>(op_W + l*HD*HD, op_b + l*HD);
    }

    mean_kernel<<<B, HD>>>();
    heads_kernel<<<B, HD>>>(card_W, card_b, at_W, at_b, src_W, src_b,
                            tgt_W, tgt_b, v1_W, v1_b, v2_W, v2_b, out);
}

// round 8
// speedup vs baseline: 2.6939x; 1.0226x over previous
#include <cuda_runtime.h>
#include <cuda_bf16.h>
#include <math.h>
#include <stdint.h>

#define B 64
#define NP 32
#define NS 72
#define HD 256
#define H 4
#define F 64
#define CSE 112
#define L 4
#define NC 110
#define EPS 1e-6f

// ---------------- device scratch (no allocations allowed) ----------------
// Referenced ONLY from device code (host symbol refs = host shadow on ATS GB300).
__device__ float g_g [B*HD];
__device__ float g_c [B*HD];
__device__ float g_x [B*NS*HD];
__device__ float g_hl[B*NS*HD];
__device__ float g_hr[B*NS*HD];
__device__ float g_ge[B*HD];
// bf16 split operands for tensor-core GEMMs
__device__ __nv_bfloat16 g_Ahi[B*NS*HD];
__device__ __nv_bfloat16 g_Alo[B*NS*HD];
__device__ __nv_bfloat16 g_Ghi[B*NS*HD];
__device__ __nv_bfloat16 g_Glo[B*NS*HD];
// weights, K-major [n][k], all layers: per layer 768 rows (Wl 256 | Wr 256 | op 256)
__device__ __nv_bfloat16 g_Bhi[L*768*HD];
__device__ __nv_bfloat16 g_Blo[L*768*HD];

// ---------------- block LN statistics over 256 threads ----------------
__device__ __forceinline__ void block_stats256(float val, float& mean, float& rstd) {
    float s = val, sq = val * val;
    #pragma unroll
    for (int o = 16; o; o >>= 1) {
        s  += __shfl_xor_sync(0xffffffffu, s,  o);
        sq += __shfl_xor_sync(0xffffffffu, sq, o);
    }
    __shared__ float ss[8], sqq[8];
    int lane = threadIdx.x & 31, w = threadIdx.x >> 5;
    if (lane == 0) { ss[w] = s; sqq[w] = sq; }
    __syncthreads();
    if (w == 0) {
        s  = (lane < 8) ? ss[lane]  : 0.f;
        sq = (lane < 8) ? sqq[lane] : 0.f;
        #pragma unroll
        for (int o = 4; o; o >>= 1) {
            s  += __shfl_xor_sync(0xffffffffu, s,  o);
            sq += __shfl_xor_sync(0xffffffffu, sq, o);
        }
        if (lane == 0) { ss[0] = s; sqq[0] = sq; }
    }
    __syncthreads();
    s = ss[0]; sq = sqq[0];
    mean = s * (1.f / 256.f);
    float var = sq * (1.f / 256.f) - mean * mean;
    rstd = rsqrtf(var + EPS);
}

// ---------------- context MLP ----------------
__global__ void ctx_kernel(const float* __restrict__ cc, const float* __restrict__ W,
                           const float* __restrict__ bias, const float* __restrict__ lns,
                           const float* __restrict__ lnb) {
    int b = blockIdx.x, d = threadIdx.x;
    __shared__ float cs[CSE];
    if (d < CSE) cs[d] = cc[b*CSE + d];
    __syncthreads();
    float acc = bias[d];
    #pragma unroll 4
    for (int k = 0; k < CSE; k++) acc += cs[k] * W[k*HD + d];
    float mean, rstd;
    block_stats256(acc, mean, rstd);
    float y = (acc - mean) * rstd * lns[d] + lnb[d];
    g_g[b*HD + d] = fmaxf(y, 0.f);
}

// ---------------- input embed ----------------
__global__ void embed_kernel(const float* __restrict__ so, const float* __restrict__ W,
                             const float* __restrict__ bias) {
    int bs = blockIdx.x; int b = bs / NS, s = bs % NS; int d = threadIdx.x;
    __shared__ float sv[NP];
    if (d < NP) sv[d] = so[(b*NP + d)*NS + s];
    __syncthreads();
    float acc = bias[d];
    #pragma unroll
    for (int p = 0; p < NP; p++) acc += sv[p] * W[p*HD + d];
    g_x[bs*HD + d] = acc;
}

// ---------------- c[b,:] = g[b] @ cp_W[l] + cp_b[l] ----------------
__global__ void cp_kernel(const float* __restrict__ W, const float* __restrict__ bias) {
    int b = blockIdx.x, d = threadIdx.x;
    __shared__ float gs[HD];
    gs[d] = g_g[b*HD + d];
    __syncthreads();
    float acc = bias[d];
    #pragma unroll 8
    for (int k = 0; k < HD; k++) acc += gs[k] * W[k*HD + d];
    g_c[b*HD + d] = acc;
}

// ---------------- h = LN(x)*s+b + c, split to bf16 hi/lo ----------------
__global__ void ln_add_kernel(const float* __restrict__ lns, const float* __restrict__ lnb) {
    int bs = blockIdx.x, d = threadIdx.x; int b = bs / NS;
    float val = g_x[bs*HD + d];
    float mean, rstd;
    block_stats256(val, mean, rstd);
    float y = (val - mean) * rstd * lns[d] + lnb[d] + g_c[b*HD + d];
    __nv_bfloat16 hh = __float2bfloat16(y);
    g_Ahi[bs*HD + d] = hh;
    g_Alo[bs*HD + d] = __float2bfloat16(y - __bfloat162float(hh));
}

// ---------------- all-layer weight transpose + bf16 split ----------------
// layer l, row n: n<256 -> Wl[l][k][n]; n<512 -> Wr[l][k][n-256]; else op_W[l][k][n-512]
__global__ void convW_all(const float* __restrict__ Wl, const float* __restrict__ Wr,
                          const float* __restrict__ Wo) {
    int n = blockIdx.x, l = blockIdx.y, k = threadIdx.x;
    const float* src; int col;
    if (n < 256)      { src = Wl + (size_t)l*HD*HD; col = n; }
    else if (n < 512) { src = Wr + (size_t)l*HD*HD; col = n - 256; }
    else              { src = Wo + (size_t)l*HD*HD; col = n - 512; }
    float v = src[k*HD + col];
    __nv_bfloat16 hh = __float2bfloat16(v);
    size_t idx = ((size_t)l*768 + n)*HD + k;
    g_Bhi[idx] = hh;
    g_Blo[idx] = __float2bfloat16(v - __bfloat162float(hh));
}

// ---------------- mma.sync bf16 GEMM: C[4608, Ntot] = A[4608,256] @ B^T ----------------
// MODE 0: A=(g_Ahi,g_Alo), C = g_hl (n<256) / g_hr, no bias.  grid (36, 8)
// MODE 1: A=(g_Ghi,g_Glo), C = g_x accumulate + bias.         grid (36, 4)
// 3-term split: AhBh + AhBl + AlBh, fp32 accum.
__device__ __forceinline__ void mma_bf16(float* c, const uint32_t* a, const uint32_t* b) {
    asm volatile(
        "mma.sync.aligned.m16n8k16.row.col.f32.bf16.bf16.f32 "
        "{%0,%1,%2,%3}, {%4,%5,%6,%7}, {%8,%9}, {%0,%1,%2,%3};"
        : "+f"(c[0]), "+f"(c[1]), "+f"(c[2]), "+f"(c[3])
        : "r"(a[0]), "r"(a[1]), "r"(a[2]), "r"(a[3]), "r"(b[0]), "r"(b[1]));
}

template<int MODE>
__global__ void __launch_bounds__(256) gemm_mma(int wrow, const float* __restrict__ bias) {
    const __nv_bfloat16* Ahi = (MODE == 0) ? g_Ahi : g_Ghi;
    const __nv_bfloat16* Alo = (MODE == 0) ? g_Alo : g_Glo;
    int tid = threadIdx.x, lane = tid & 31, warp = tid >> 5;
    int wm = warp >> 1, wn = warp & 1;              // 4 x 2 warp grid
    int m0   = blockIdx.x * 128 + wm * 32;
    int nloc = blockIdx.y * 64 + wn * 32;           // n within this GEMM
    const __nv_bfloat16* Bhi = g_Bhi + (size_t)(wrow + nloc) * HD;
    const __nv_bfloat16* Blo = g_Blo + (size_t)(wrow + nloc) * HD;
    int lr = lane >> 2, lc = (lane & 3) * 2;

    float acc[2][4][4];
    #pragma unroll
    for (int mt = 0; mt < 2; mt++)
        #pragma unroll
        for (int nt = 0; nt < 4; nt++)
            #pragma unroll
            for (int c = 0; c < 4; c++) acc[mt][nt][c] = 0.f;

    for (int k0 = 0; k0 < 256; k0 += 16) {
        uint32_t ah[2][4], al[2][4], bh[4][2], bl[4][2];
        #pragma unroll
        for (int mt = 0; mt < 2; mt++) {
            size_t base = (size_t)(m0 + mt*16 + lr) * HD + k0 + lc;
            const uint32_t* ph = (const uint32_t*)(Ahi + base);
            const uint32_t* pl = (const uint32_t*)(Alo + base);
            ah[mt][0] = ph[0];    ah[mt][1] = ph[1024];   // +8 rows = 8*256 bf16 = 1024 u32
            ah[mt][2] = ph[4];    ah[mt][3] = ph[1028];   // +8 k    = 4 u32
            al[mt][0] = pl[0];    al[mt][1] = pl[1024];
            al[mt][2] = pl[4];    al[mt][3] = pl[1028];
        }
        #pragma unroll
        for (int nt = 0; nt < 4; nt++) {
            size_t base = (size_t)(nt*8 + lr) * HD + k0 + lc;
            const uint32_t* ph = (const uint32_t*)(Bhi + base);
            const uint32_t* pl = (const uint32_t*)(Blo + base);
            bh[nt][0] = ph[0];  bh[nt][1] = ph[4];
            bl[nt][0] = pl[0];  bl[nt][1] = pl[4];
        }
        #pragma unroll
        for (int mt = 0; mt < 2; mt++)
            #pragma unroll
            for (int nt = 0; nt < 4; nt++) {
                mma_bf16(acc[mt][nt], ah[mt], bh[nt]);
                mma_bf16(acc[mt][nt], ah[mt], bl[nt]);
                mma_bf16(acc[mt][nt], al[mt], bh[nt]);
            }
    }

    // epilogue: c0,c1 -> (row, n), (row, n+1); c2,c3 -> (row+8, ...)
    #pragma unroll
    for (int mt = 0; mt < 2; mt++) {
        int r = m0 + mt*16 + lr;
        #pragma unroll
        for (int nt = 0; nt < 4; nt++) {
            int gn = nloc + nt*8 + lc;
            if (MODE == 0) {
                float* C = (gn < 256) ? g_hl : g_hr;
                int cc = gn & 255;
                C[(size_t)r*HD + cc]           = acc[mt][nt][0];
                C[(size_t)r*HD + cc + 1]       = acc[mt][nt][1];
                C[(size_t)(r+8)*HD + cc]       = acc[mt][nt][2];
                C[(size_t)(r+8)*HD + cc + 1]   = acc[mt][nt][3];
            } else {
                g_x[(size_t)r*HD + gn]         += acc[mt][nt][0] + bias[gn];
                g_x[(size_t)r*HD + gn + 1]     += acc[mt][nt][1] + bias[gn + 1];
                g_x[(size_t)(r+8)*HD + gn]     += acc[mt][nt][2] + bias[gn];
                g_x[(size_t)(r+8)*HD + gn + 1] += acc[mt][nt][3] + bias[gn + 1];
            }
        }
    }
}

// ---------------- GATv2 attention, parallel over (batch, i-chunk) ----------------
#define TI 8
#define ATTN_SMEM ((NS*HD + TI*HD + TI*NS*H + TI*NS) * sizeof(float))
__global__ void attn_kernel(const float* __restrict__ adj, const float* __restrict__ Wa) {
    int b = blockIdx.x;
    int i0 = blockIdx.y * TI;
    int tid = threadIdx.x, lane = tid & 31, warp = tid >> 5;
    extern __shared__ float smf[];
    float* hrs  = smf;
    float* hls  = hrs + NS*HD;
    float* sc   = hls + TI*HD;
    float* adjr = sc + TI*NS*H;
    __shared__ float wa_s[H*F];
    wa_s[tid] = Wa[tid];
    const float* src_r = g_hr + b*NS*HD;
    const float* src_l = g_hl + (b*NS + i0)*HD;
    for (int k = tid; k < NS*HD; k += 256) hrs[k] = src_r[k];
    for (int k = tid; k < TI*HD; k += 256) hls[k] = src_l[k];
    for (int k = tid; k < TI*NS; k += 256) adjr[k] = adj[(i0 + k/NS)*NS + (k % NS)];
    __syncthreads();

    for (int e = warp; e < TI*NS*H; e += 8) {
        int i = e / (NS*H);
        int rem = e - i*(NS*H);
        int j = rem / H, h = rem - j*H;
        float p = 0.f;
        #pragma unroll
        for (int fc = 0; fc < F; fc += 32) {
            int f = fc + lane;
            float v = hls[i*HD + h*F + f] + hrs[j*HD + h*F + f];
            v = (v > 0.f) ? v : 0.2f * v;
            p += wa_s[h*F + f] * v;
        }
        #pragma unroll
        for (int o = 16; o; o >>= 1) p += __shfl_xor_sync(0xffffffffu, p, o);
        if (lane == 0) sc[(i*NS + j)*H + h] = (adjr[i*NS + j] > 0.f) ? p : -1e9f;
    }
    __syncthreads();

    for (int p = warp; p < TI*H; p += 8) {
        int i = p >> 2, h = p & 3;
        float m = -1e30f;
        for (int j = lane; j < NS; j += 32) m = fmaxf(m, sc[(i*NS + j)*H + h]);
        #pragma unroll
        for (int o = 16; o; o >>= 1) m = fmaxf(m, __shfl_xor_sync(0xffffffffu, m, o));
        float s = 0.f;
        for (int j = lane; j < NS; j += 32) {
            float e2 = expf(sc[(i*NS + j)*H + h] - m);
            sc[(i*NS + j)*H + h] = e2; s += e2;
        }
        #pragma unroll
        for (int o = 16; o; o >>= 1) s += __shfl_xor_sync(0xffffffffu, s, o);
        float inv = 1.f / s;
        for (int j = lane; j < NS; j += 32) sc[(i*NS + j)*H + h] *= inv;
    }
    __syncthreads();

    int d = tid, h = d >> 6;
    float acc[TI] = {};
    for (int j = 0; j < NS; j++) {
        float hv = hrs[j*HD + d];
        #pragma unroll
        for (int i = 0; i < TI; i++) acc[i] += sc[(i*NS + j)*H + h] * hv;
    }
    #pragma unroll
    for (int i = 0; i < TI; i++) {
        float v = acc[i];
        __nv_bfloat16 hh = __float2bfloat16(v);
        size_t idx = (size_t)(b*NS + i0 + i)*HD + d;
        g_Ghi[idx] = hh;
        g_Glo[idx] = __float2bfloat16(v - __bfloat162float(hh));
    }
}

// ---------------- mean pool over NS ----------------
__global__ void mean_kernel() {
    int b = blockIdx.x, d = threadIdx.x;
    float acc = 0.f;
    #pragma unroll 8
    for (int s = 0; s < NS; s++) acc += g_x[(b*NS + s)*HD + d];
    g_ge[b*HD + d] = acc * (1.f / (float)NS);
}

// ---------------- output heads ----------------
#define OUT_CARD 0
#define OUT_AT   (B*NC)
#define OUT_SRC  (OUT_AT + B*3)
#define OUT_TGT  (OUT_SRC + B*NS)
#define OUT_VAL  (OUT_TGT + B*NS)
__global__ void heads_kernel(const float* __restrict__ cW, const float* __restrict__ cb,
                             const float* __restrict__ aW, const float* __restrict__ ab,
                             const float* __restrict__ sW, const float* __restrict__ sb,
                             const float* __restrict__ tW, const float* __restrict__ tb,
                             const float* __restrict__ v1W, const float* __restrict__ v1b,
                             const float* __restrict__ v2W, const float* __restrict__ v2b,
                             float* __restrict__ out) {
    int b = blockIdx.x, tid = threadIdx.x;
    __shared__ float ge[HD];
    __shared__ float vh[128];
    __shared__ float vpart[4];
    ge[tid] = g_ge[b*HD + tid];
    __syncthreads();
    if (tid < NC) {
        float a = cb[tid];
        for (int k = 0; k < HD; k++) a += ge[k] * cW[k*NC + tid];
        out[OUT_CARD + b*NC + tid] = a;
    }
    if (tid < 3) {
        float a = ab[tid];
        for (int k = 0; k < HD; k++) a += ge[k] * aW[k*3 + tid];
        out[OUT_AT + b*3 + tid] = a;
    }
    if (tid < NS) {
        float a = sb[tid], t = tb[tid];
        for (int k = 0; k < HD; k++) { a += ge[k] * sW[k*NS + tid]; t += ge[k] * tW[k*NS + tid]; }
        out[OUT_SRC + b*NS + tid] = a;
        out[OUT_TGT + b*NS + tid] = t;
    }
    if (tid < 128) {
        float a = v1b[tid];
        for (int k = 0; k < HD; k++) a += ge[k] * v1W[k*128 + tid];
        vh[tid] = fmaxf(a, 0.f);
    }
    __syncthreads();
    if (tid < 128) {
        float p = vh[tid] * v2W[tid];
        #pragma unroll
        for (int o = 16; o; o >>= 1) p += __shfl_xor_sync(0xffffffffu, p, o);
        if ((tid & 31) == 0) vpart[tid >> 5] = p;
    }
    __syncthreads();
    if (tid == 0) {
        float s = vpart[0] + vpart[1] + vpart[2] + vpart[3] + v2b[0];
        out[OUT_VAL + b] = tanhf(s);
    }
}

// ---------------- launch ----------------
extern "C" void kernel_launch(void* const* d_in, const int* in_sizes, int n_in,
                              void* d_out, int out_size) {
    const float* spatial_obs = (const float*)d_in[0];
    const float* card_ctx    = (const float*)d_in[1];
    const float* adj         = (const float*)d_in[2];
    const float* ctx_W  = (const float*)d_in[3];
    const float* ctx_b  = (const float*)d_in[4];
    const float* lnc_s  = (const float*)d_in[5];
    const float* lnc_b  = (const float*)d_in[6];
    const float* in_W   = (const float*)d_in[7];
    const float* in_b   = (const float*)d_in[8];
    const float* lnp_s  = (const float*)d_in[9];
    const float* lnp_b  = (const float*)d_in[10];
    const float* cp_W   = (const float*)d_in[11];
    const float* cp_b   = (const float*)d_in[12];
    const float* Wl     = (const float*)d_in[13];
    const float* Wr     = (const float*)d_in[14];
    const float* Wa     = (const float*)d_in[15];
    const float* op_W   = (const float*)d_in[16];
    const float* op_b   = (const float*)d_in[17];
    const float* card_W = (const float*)d_in[18];
    const float* card_b = (const float*)d_in[19];
    const float* at_W   = (const float*)d_in[20];
    const float* at_b   = (const float*)d_in[21];
    const float* src_W  = (const float*)d_in[22];
    const float* src_b  = (const float*)d_in[23];
    const float* tgt_W  = (const float*)d_in[24];
    const float* tgt_b  = (const float*)d_in[25];
    const float* v1_W   = (const float*)d_in[26];
    const float* v1_b   = (const float*)d_in[27];
    const float* v2_W   = (const float*)d_in[28];
    const float* v2_b   = (const float*)d_in[29];
    float* out = (float*)d_out;

    cudaFuncSetAttribute(attn_kernel, cudaFuncAttributeMaxDynamicSharedMemorySize, ATTN_SMEM);

    ctx_kernel<<<B, HD>>>(card_ctx, ctx_W, ctx_b, lnc_s, lnc_b);
    embed_kernel<<<B*NS, HD>>>(spatial_obs, in_W, in_b);
    convW_all<<<dim3(768, L), 256>>>(Wl, Wr, op_W);

    dim3 agrid(B, NS/TI);
    dim3 glr(36, 8);   // fused Wl|Wr, Ntot=512
    dim3 gop(36, 4);   // op_W,       Ntot=256
    for (int l = 0; l < L; l++) {
        cp_kernel<<<B, HD>>>(cp_W + l*HD*HD, cp_b + l*HD);
        ln_add_kernel<<<B*NS, HD>>>(lnp_s + l*HD, lnp_b + l*HD);
        gemm_mma<0><<<glr, 256>>>(l*768, nullptr);
        attn_kernel<<<agrid, 256, ATTN_SMEM>>>(adj, Wa + l*H*F);
        gemm_mma<1><<<gop, 256>>>(l*768 + 512, op_b + l*HD);
    }

    mean_kernel<<<B, HD>>>();
    heads_kernel<<<B, HD>>>(card_W, card_b, at_W, at_b, src_W, src_b,
                            tgt_W, tgt_b, v1_W, v1_b, v2_W, v2_b, out);
}

// round 9
// speedup vs baseline: 3.2001x; 1.1879x over previous
#include <cuda_runtime.h>
#include <cuda_bf16.h>
#include <math.h>
#include <stdint.h>

#define B 64
#define NP 32
#define NS 72
#define HD 256
#define H 4
#define F 64
#define CSE 112
#define L 4
#define NC 110
#define EPS 1e-6f

// ---------------- device scratch (no allocations allowed) ----------------
// Referenced ONLY from device code (host symbol refs = host shadow on ATS GB300).
__device__ float g_g [B*HD];
__device__ float g_c [L*B*HD];
__device__ float g_x [B*NS*HD];
__device__ float g_hl[B*NS*HD];
__device__ float g_hr[B*NS*HD];
__device__ float g_ge[B*HD];
// bf16 split operands for tensor-core GEMMs
__device__ __nv_bfloat16 g_Ahi[B*NS*HD];
__device__ __nv_bfloat16 g_Alo[B*NS*HD];
__device__ __nv_bfloat16 g_Ghi[B*NS*HD];
__device__ __nv_bfloat16 g_Glo[B*NS*HD];
// weights, K-major [n][k], per layer 768 rows (Wl 256 | Wr 256 | op 256)
__device__ __nv_bfloat16 g_Bhi[L*768*HD];
__device__ __nv_bfloat16 g_Blo[L*768*HD];

#define SWZ128(bo) ((bo) ^ (((bo) >> 3) & 0x70))

// ---------------- block LN statistics over 256 threads ----------------
__device__ __forceinline__ void block_stats256(float val, float& mean, float& rstd) {
    float s = val, sq = val * val;
    #pragma unroll
    for (int o = 16; o; o >>= 1) {
        s  += __shfl_xor_sync(0xffffffffu, s,  o);
        sq += __shfl_xor_sync(0xffffffffu, sq, o);
    }
    __shared__ float ss[8], sqq[8];
    int lane = threadIdx.x & 31, w = threadIdx.x >> 5;
    if (lane == 0) { ss[w] = s; sqq[w] = sq; }
    __syncthreads();
    if (w == 0) {
        s  = (lane < 8) ? ss[lane]  : 0.f;
        sq = (lane < 8) ? sqq[lane] : 0.f;
        #pragma unroll
        for (int o = 4; o; o >>= 1) {
            s  += __shfl_xor_sync(0xffffffffu, s,  o);
            sq += __shfl_xor_sync(0xffffffffu, sq, o);
        }
        if (lane == 0) { ss[0] = s; sqq[0] = sq; }
    }
    __syncthreads();
    s = ss[0]; sq = sqq[0];
    mean = s * (1.f / 256.f);
    float var = sq * (1.f / 256.f) - mean * mean;
    rstd = rsqrtf(var + EPS);
}

// ---------------- context MLP ----------------
__global__ void ctx_kernel(const float* __restrict__ cc, const float* __restrict__ W,
                           const float* __restrict__ bias, const float* __restrict__ lns,
                           const float* __restrict__ lnb) {
    int b = blockIdx.x, d = threadIdx.x;
    __shared__ float cs[CSE];
    if (d < CSE) cs[d] = cc[b*CSE + d];
    __syncthreads();
    float acc = bias[d];
    #pragma unroll 4
    for (int k = 0; k < CSE; k++) acc += cs[k] * W[k*HD + d];
    float mean, rstd;
    block_stats256(acc, mean, rstd);
    float y = (acc - mean) * rstd * lns[d] + lnb[d];
    g_g[b*HD + d] = fmaxf(y, 0.f);
}

// ---------------- input embed ----------------
__global__ void embed_kernel(const float* __restrict__ so, const float* __restrict__ W,
                             const float* __restrict__ bias) {
    int bs = blockIdx.x; int b = bs / NS, s = bs % NS; int d = threadIdx.x;
    __shared__ float sv[NP];
    if (d < NP) sv[d] = so[(b*NP + d)*NS + s];
    __syncthreads();
    float acc = bias[d];
    #pragma unroll
    for (int p = 0; p < NP; p++) acc += sv[p] * W[p*HD + d];
    g_x[bs*HD + d] = acc;
}

// ---------------- c[l,b,:] = g[b] @ cp_W[l] + cp_b[l], ALL layers in one launch ----------------
__global__ void cp_all_kernel(const float* __restrict__ cp_W, const float* __restrict__ cp_b) {
    int b = blockIdx.x, l = blockIdx.y, d = threadIdx.x;
    __shared__ float gs[HD];
    gs[d] = g_g[b*HD + d];
    __syncthreads();
    const float* W = cp_W + (size_t)l*HD*HD;
    float acc = cp_b[l*HD + d];
    #pragma unroll 16
    for (int k = 0; k < HD; k++) acc += gs[k] * W[k*HD + d];
    g_c[(l*B + b)*HD + d] = acc;
}

// ---------------- h = LN(x)*s+b + c, split to bf16 hi/lo ----------------
__global__ void ln_add_kernel(const float* __restrict__ lns, const float* __restrict__ lnb, int l) {
    int bs = blockIdx.x, d = threadIdx.x; int b = bs / NS;
    float val = g_x[bs*HD + d];
    float mean, rstd;
    block_stats256(val, mean, rstd);
    float y = (val - mean) * rstd * lns[d] + lnb[d] + g_c[(l*B + b)*HD + d];
    __nv_bfloat16 hh = __float2bfloat16(y);
    g_Ahi[bs*HD + d] = hh;
    g_Alo[bs*HD + d] = __float2bfloat16(y - __bfloat162float(hh));
}

// ---------------- all-layer weight transpose + bf16 split (tiled, coalesced) ----------------
// grid (8 ktile, 8 ntile, 12 = 4 layers x {Wl,Wr,Wo}), block (32, 8)
__global__ void convW_all(const float* __restrict__ Wl, const float* __restrict__ Wr,
                          const float* __restrict__ Wo) {
    __shared__ float t[32][33];
    int m = blockIdx.z; int l = m / 3, sel = m - l*3;
    const float* src = (sel == 0 ? Wl : sel == 1 ? Wr : Wo) + (size_t)l*HD*HD;
    int k0 = blockIdx.x*32, n0 = blockIdx.y*32;
    int x = threadIdx.x, y = threadIdx.y;
    #pragma unroll
    for (int yy = y; yy < 32; yy += 8)
        t[yy][x] = src[(size_t)(k0 + yy)*HD + n0 + x];   // coalesced along n
    __syncthreads();
    int drow0 = l*768 + sel*256 + n0;
    #pragma unroll
    for (int yy = y; yy < 32; yy += 8) {
        float v = t[x][yy];                               // k = k0+x, n = n0+yy
        __nv_bfloat16 hh = __float2bfloat16(v);
        size_t idx = (size_t)(drow0 + yy)*HD + k0 + x;    // coalesced along k
        g_Bhi[idx] = hh;
        g_Blo[idx] = __float2bfloat16(v - __bfloat162float(hh));
    }
}

// ---------------- mma.sync bf16 GEMM, smem-staged ----------------
// C[4608, Ntot] = A[4608,256] @ B^T, 3-term split AhBh+AhBl+AlBh, fp32 accum.
// MODE 0: A=(g_Ahi,g_Alo), C = g_hl (n<256)/g_hr, no bias.  grid (36, 8)
// MODE 1: A=(g_Ghi,g_Glo), C = g_x accumulate + bias.       grid (36, 4)
// Block 256 thr = 8 warps (4x2), warp tile 32x32, K-chunks of 64.
__device__ __forceinline__ void mma_bf16(float* c, const uint32_t* a, const uint32_t* b) {
    asm volatile(
        "mma.sync.aligned.m16n8k16.row.col.f32.bf16.bf16.f32 "
        "{%0,%1,%2,%3}, {%4,%5,%6,%7}, {%8,%9}, {%0,%1,%2,%3};"
        : "+f"(c[0]), "+f"(c[1]), "+f"(c[2]), "+f"(c[3])
        : "r"(a[0]), "r"(a[1]), "r"(a[2]), "r"(a[3]), "r"(b[0]), "r"(b[1]));
}
#define GSM_TOTAL 49152

template<int MODE>
__global__ void __launch_bounds__(256) gemm_mma(int wrow, const float* __restrict__ bias) {
    extern __shared__ char smc[];
    char* sAh = smc;            // 128 rows x 128B (64 bf16), swizzled
    char* sAl = smc + 16384;
    char* sBh = smc + 32768;    // 64 rows x 128B
    char* sBl = smc + 40960;
    const __nv_bfloat16* Ahi = (MODE == 0) ? g_Ahi : g_Ghi;
    const __nv_bfloat16* Alo = (MODE == 0) ? g_Alo : g_Glo;
    int tid = threadIdx.x, lane = tid & 31, warp = tid >> 5;
    int wm = warp >> 1, wn = warp & 1;
    int m0   = blockIdx.x * 128;
    int nloc = blockIdx.y * 64;
    const __nv_bfloat16* Bhi = g_Bhi + (size_t)(wrow + nloc) * HD;
    const __nv_bfloat16* Blo = g_Blo + (size_t)(wrow + nloc) * HD;
    int lr = lane >> 2, lc2 = (lane & 3) * 2;

    float acc[2][4][4];
    #pragma unroll
    for (int mt = 0; mt < 2; mt++)
        #pragma unroll
        for (int nt = 0; nt < 4; nt++)
            #pragma unroll
            for (int c = 0; c < 4; c++) acc[mt][nt][c] = 0.f;

    int arow = tid >> 1, ahalf = tid & 1;     // A: 2 thr/row, 64B each
    int brow = tid >> 2, bq = tid & 3;        // B: 4 thr/row, 32B each

    for (int kc = 0; kc < 4; kc++) {
        if (kc) __syncthreads();
        {
            const uint4* gh = (const uint4*)(Ahi + (size_t)(m0 + arow)*HD + kc*64 + ahalf*32);
            const uint4* gl = (const uint4*)(Alo + (size_t)(m0 + arow)*HD + kc*64 + ahalf*32);
            #pragma unroll
            for (int c = 0; c < 4; c++) {
                uint32_t sw = SWZ128((uint32_t)(arow*128 + ahalf*64 + c*16));
                *(uint4*)(sAh + sw) = gh[c];
                *(uint4*)(sAl + sw) = gl[c];
            }
            const uint4* bhp = (const uint4*)(Bhi + (size_t)brow*HD + kc*64 + bq*16);
            const uint4* blp = (const uint4*)(Blo + (size_t)brow*HD + kc*64 + bq*16);
            #pragma unroll
            for (int c = 0; c < 2; c++) {
                uint32_t sw = SWZ128((uint32_t)(brow*128 + bq*32 + c*16));
                *(uint4*)(sBh + sw) = bhp[c];
                *(uint4*)(sBl + sw) = blp[c];
            }
        }
        __syncthreads();
        #pragma unroll
        for (int ks = 0; ks < 4; ks++) {
            int kk = ks*16;
            uint32_t ah[2][4], al[2][4], bh[4][2], bl[4][2];
            #pragma unroll
            for (int mt = 0; mt < 2; mt++) {
                int r = wm*32 + mt*16 + lr;
                uint32_t o0 = SWZ128((uint32_t)(r*128 + (kk + lc2)*2));
                uint32_t o1 = SWZ128((uint32_t)((r + 8)*128 + (kk + lc2)*2));
                uint32_t o2 = SWZ128((uint32_t)(r*128 + (kk + lc2 + 8)*2));
                uint32_t o3 = SWZ128((uint32_t)((r + 8)*128 + (kk + lc2 + 8)*2));
                ah[mt][0] = *(uint32_t*)(sAh + o0);
                ah[mt][1] = *(uint32_t*)(sAh + o1);
                ah[mt][2] = *(uint32_t*)(sAh + o2);
                ah[mt][3] = *(uint32_t*)(sAh + o3);
                al[mt][0] = *(uint32_t*)(sAl + o0);
                al[mt][1] = *(uint32_t*)(sAl + o1);
                al[mt][2] = *(uint32_t*)(sAl + o2);
                al[mt][3] = *(uint32_t*)(sAl + o3);
            }
            #pragma unroll
            for (int nt = 0; nt < 4; nt++) {
                int r = wn*32 + nt*8 + lr;
                uint32_t o0 = SWZ128((uint32_t)(r*128 + (kk + lc2)*2));
                uint32_t o1 = SWZ128((uint32_t)(r*128 + (kk + lc2 + 8)*2));
                bh[nt][0] = *(uint32_t*)(sBh + o0);
                bh[nt][1] = *(uint32_t*)(sBh + o1);
                bl[nt][0] = *(uint32_t*)(sBl + o0);
                bl[nt][1] = *(uint32_t*)(sBl + o1);
            }
            #pragma unroll
            for (int mt = 0; mt < 2; mt++)
                #pragma unroll
                for (int nt = 0; nt < 4; nt++) {
                    mma_bf16(acc[mt][nt], ah[mt], bh[nt]);
                    mma_bf16(acc[mt][nt], ah[mt], bl[nt]);
                    mma_bf16(acc[mt][nt], al[mt], bh[nt]);
                }
        }
    }

    #pragma unroll
    for (int mt = 0; mt < 2; mt++) {
        int r = m0 + wm*32 + mt*16 + lr;
        #pragma unroll
        for (int nt = 0; nt < 4; nt++) {
            int gn = nloc + wn*32 + nt*8 + lc2;
            if (MODE == 0) {
                float* C = (gn < 256) ? g_hl : g_hr;
                int cc = gn & 255;
                C[(size_t)r*HD + cc]           = acc[mt][nt][0];
                C[(size_t)r*HD + cc + 1]       = acc[mt][nt][1];
                C[(size_t)(r+8)*HD + cc]       = acc[mt][nt][2];
                C[(size_t)(r+8)*HD + cc + 1]   = acc[mt][nt][3];
            } else {
                g_x[(size_t)r*HD + gn]         += acc[mt][nt][0] + bias[gn];
                g_x[(size_t)r*HD + gn + 1]     += acc[mt][nt][1] + bias[gn + 1];
                g_x[(size_t)(r+8)*HD + gn]     += acc[mt][nt][2] + bias[gn];
                g_x[(size_t)(r+8)*HD + gn + 1] += acc[mt][nt][3] + bias[gn + 1];
            }
        }
    }
}

// ---------------- GATv2 attention, parallel over (batch, i-chunk) ----------------
#define TI 8
#define ATTN_SMEM ((NS*HD + TI*HD + TI*NS*H + TI*NS) * sizeof(float))
__global__ void attn_kernel(const float* __restrict__ adj, const float* __restrict__ Wa) {
    int b = blockIdx.x;
    int i0 = blockIdx.y * TI;
    int tid = threadIdx.x, lane = tid & 31, warp = tid >> 5;
    extern __shared__ float smf[];
    float* hrs  = smf;
    float* hls  = hrs + NS*HD;
    float* sc   = hls + TI*HD;
    float* adjr = sc + TI*NS*H;
    __shared__ float wa_s[H*F];
    wa_s[tid] = Wa[tid];
    const float* src_r = g_hr + b*NS*HD;
    const float* src_l = g_hl + (b*NS + i0)*HD;
    for (int k = tid; k < NS*HD; k += 256) hrs[k] = src_r[k];
    for (int k = tid; k < TI*HD; k += 256) hls[k] = src_l[k];
    for (int k = tid; k < TI*NS; k += 256) adjr[k] = adj[(i0 + k/NS)*NS + (k % NS)];
    __syncthreads();

    for (int e = warp; e < TI*NS*H; e += 8) {
        int i = e / (NS*H);
        int rem = e - i*(NS*H);
        int j = rem / H, h = rem - j*H;
        float p = 0.f;
        #pragma unroll
        for (int fc = 0; fc < F; fc += 32) {
            int f = fc + lane;
            float v = hls[i*HD + h*F + f] + hrs[j*HD + h*F + f];
            v = (v > 0.f) ? v : 0.2f * v;
            p += wa_s[h*F + f] * v;
        }
        #pragma unroll
        for (int o = 16; o; o >>= 1) p += __shfl_xor_sync(0xffffffffu, p, o);
        if (lane == 0) sc[(i*NS + j)*H + h] = (adjr[i*NS + j] > 0.f) ? p : -1e9f;
    }
    __syncthreads();

    for (int p = warp; p < TI*H; p += 8) {
        int i = p >> 2, h = p & 3;
        float m = -1e30f;
        for (int j = lane; j < NS; j += 32) m = fmaxf(m, sc[(i*NS + j)*H + h]);
        #pragma unroll
        for (int o = 16; o; o >>= 1) m = fmaxf(m, __shfl_xor_sync(0xffffffffu, m, o));
        float s = 0.f;
        for (int j = lane; j < NS; j += 32) {
            float e2 = expf(sc[(i*NS + j)*H + h] - m);
            sc[(i*NS + j)*H + h] = e2; s += e2;
        }
        #pragma unroll
        for (int o = 16; o; o >>= 1) s += __shfl_xor_sync(0xffffffffu, s, o);
        float inv = 1.f / s;
        for (int j = lane; j < NS; j += 32) sc[(i*NS + j)*H + h] *= inv;
    }
    __syncthreads();

    int d = tid, h = d >> 6;
    float acc[TI] = {};
    for (int j = 0; j < NS; j++) {
        float hv = hrs[j*HD + d];
        #pragma unroll
        for (int i = 0; i < TI; i++) acc[i] += sc[(i*NS + j)*H + h] * hv;
    }
    #pragma unroll
    for (int i = 0; i < TI; i++) {
        float v = acc[i];
        __nv_bfloat16 hh = __float2bfloat16(v);
        size_t idx = (size_t)(b*NS + i0 + i)*HD + d;
        g_Ghi[idx] = hh;
        g_Glo[idx] = __float2bfloat16(v - __bfloat162float(hh));
    }
}

// ---------------- mean pool over NS ----------------
__global__ void mean_kernel() {
    int b = blockIdx.x, d = threadIdx.x;
    float acc = 0.f;
    #pragma unroll 8
    for (int s = 0; s < NS; s++) acc += g_x[(b*NS + s)*HD + d];
    g_ge[b*HD + d] = acc * (1.f / (float)NS);
}

// ---------------- output heads ----------------
#define OUT_CARD 0
#define OUT_AT   (B*NC)
#define OUT_SRC  (OUT_AT + B*3)
#define OUT_TGT  (OUT_SRC + B*NS)
#define OUT_VAL  (OUT_TGT + B*NS)
__global__ void heads_kernel(const float* __restrict__ cW, const float* __restrict__ cb,
                             const float* __restrict__ aW, const float* __restrict__ ab,
                             const float* __restrict__ sW, const float* __restrict__ sb,
                             const float* __restrict__ tW, const float* __restrict__ tb,
                             const float* __restrict__ v1W, const float* __restrict__ v1b,
                             const float* __restrict__ v2W, const float* __restrict__ v2b,
                             float* __restrict__ out) {
    int b = blockIdx.x, tid = threadIdx.x;
    __shared__ float ge[HD];
    __shared__ float vh[128];
    __shared__ float vpart[4];
    ge[tid] = g_ge[b*HD + tid];
    __syncthreads();
    if (tid < NC) {
        float a = cb[tid];
        for (int k = 0; k < HD; k++) a += ge[k] * cW[k*NC + tid];
        out[OUT_CARD + b*NC + tid] = a;
    }
    if (tid < 3) {
        float a = ab[tid];
        for (int k = 0; k < HD; k++) a += ge[k] * aW[k*3 + tid];
        out[OUT_AT + b*3 + tid] = a;
    }
    if (tid < NS) {
        float a = sb[tid], t = tb[tid];
        for (int k = 0; k < HD; k++) { a += ge[k] * sW[k*NS + tid]; t += ge[k] * tW[k*NS + tid]; }
        out[OUT_SRC + b*NS + tid] = a;
        out[OUT_TGT + b*NS + tid] = t;
    }
    if (tid < 128) {
        float a = v1b[tid];
        for (int k = 0; k < HD; k++) a += ge[k] * v1W[k*128 + tid];
        vh[tid] = fmaxf(a, 0.f);
    }
    __syncthreads();
    if (tid < 128) {
        float p = vh[tid] * v2W[tid];
        #pragma unroll
        for (int o = 16; o; o >>= 1) p += __shfl_xor_sync(0xffffffffu, p, o);
        if ((tid & 31) == 0) vpart[tid >> 5] = p;
    }
    __syncthreads();
    if (tid == 0) {
        float s = vpart[0] + vpart[1] + vpart[2] + vpart[3] + v2b[0];
        out[OUT_VAL + b] = tanhf(s);
    }
}

// ---------------- launch ----------------
extern "C" void kernel_launch(void* const* d_in, const int* in_sizes, int n_in,
                              void* d_out, int out_size) {
    const float* spatial_obs = (const float*)d_in[0];
    const float* card_ctx    = (const float*)d_in[1];
    const float* adj         = (const float*)d_in[2];
    const float* ctx_W  = (const float*)d_in[3];
    const float* ctx_b  = (const float*)d_in[4];
    const float* lnc_s  = (const float*)d_in[5];
    const float* lnc_b  = (const float*)d_in[6];
    const float* in_W   = (const float*)d_in[7];
    const float* in_b   = (const float*)d_in[8];
    const float* lnp_s  = (const float*)d_in[9];
    const float* lnp_b  = (const float*)d_in[10];
    const float* cp_W   = (const float*)d_in[11];
    const float* cp_b   = (const float*)d_in[12];
    const float* Wl     = (const float*)d_in[13];
    const float* Wr     = (const float*)d_in[14];
    const float* Wa     = (const float*)d_in[15];
    const float* op_W   = (const float*)d_in[16];
    const float* op_b   = (const float*)d_in[17];
    const float* card_W = (const float*)d_in[18];
    const float* card_b = (const float*)d_in[19];
    const float* at_W   = (const float*)d_in[20];
    const float* at_b   = (const float*)d_in[21];
    const float* src_W  = (const float*)d_in[22];
    const float* src_b  = (const float*)d_in[23];
    const float* tgt_W  = (const float*)d_in[24];
    const float* tgt_b  = (const float*)d_in[25];
    const float* v1_W   = (const float*)d_in[26];
    const float* v1_b   = (const float*)d_in[27];
    const float* v2_W   = (const float*)d_in[28];
    const float* v2_b   = (const float*)d_in[29];
    float* out = (float*)d_out;

    cudaFuncSetAttribute(attn_kernel, cudaFuncAttributeMaxDynamicSharedMemorySize, ATTN_SMEM);
    cudaFuncSetAttribute(gemm_mma<0>, cudaFuncAttributeMaxDynamicSharedMemorySize, GSM_TOTAL);
    cudaFuncSetAttribute(gemm_mma<1>, cudaFuncAttributeMaxDynamicSharedMemorySize, GSM_TOTAL);

    ctx_kernel<<<B, HD>>>(card_ctx, ctx_W, ctx_b, lnc_s, lnc_b);
    embed_kernel<<<B*NS, HD>>>(spatial_obs, in_W, in_b);
    convW_all<<<dim3(8, 8, 12), dim3(32, 8)>>>(Wl, Wr, op_W);
    cp_all_kernel<<<dim3(B, L), HD>>>(cp_W, cp_b);

    dim3 agrid(B, NS/TI);
    dim3 glr(36, 8);   // fused Wl|Wr, Ntot=512
    dim3 gop(36, 4);   // op_W,       Ntot=256
    for (int l = 0; l < L; l++) {
        ln_add_kernel<<<B*NS, HD>>>(lnp_s + l*HD, lnp_b + l*HD, l);
        gemm_mma<0><<<glr, 256, GSM_TOTAL>>>(l*768, nullptr);
        attn_kernel<<<agrid, 256, ATTN_SMEM>>>(adj, Wa + l*H*F);
        gemm_mma<1><<<gop, 256, GSM_TOTAL>>>(l*768 + 512, op_b + l*HD);
    }

    mean_kernel<<<B, HD>>>();
    heads_kernel<<<B, HD>>>(card_W, card_b, at_W, at_b, src_W, src_b,
                            tgt_W, tgt_b, v1_W, v1_b, v2_W, v2_b, out);
}

// round 11
// speedup vs baseline: 3.2060x; 1.0019x over previous
#include <cuda_runtime.h>
#include <cuda_bf16.h>
#include <math.h>
#include <stdint.h>

#define B 64
#define NP 32
#define NS 72
#define HD 256
#define H 4
#define F 64
#define CSE 112
#define L 4
#define NC 110
#define EPS 1e-6f

// ---------------- device scratch (no allocations allowed) ----------------
// Referenced ONLY from device code (host symbol refs = host shadow on ATS GB300).
__device__ float g_g [B*HD];
__device__ float g_c [L*B*HD];
__device__ float g_x [B*NS*HD];
__device__ float g_hl[B*NS*HD];
__device__ float g_hr[B*NS*HD];
__device__ float g_ge[B*HD];
// bf16 split operands for tensor-core GEMMs
__device__ __nv_bfloat16 g_Ahi[B*NS*HD];
__device__ __nv_bfloat16 g_Alo[B*NS*HD];
__device__ __nv_bfloat16 g_Ghi[B*NS*HD];
__device__ __nv_bfloat16 g_Glo[B*NS*HD];
// weights, K-major [n][k], per layer 768 rows (Wl 256 | Wr 256 | op 256)
__device__ __nv_bfloat16 g_Bhi[L*768*HD];
__device__ __nv_bfloat16 g_Blo[L*768*HD];

#define SWZ128(bo) ((bo) ^ (((bo) >> 3) & 0x70))

__device__ __forceinline__ uint32_t smem_u32(const void* p) {
    uint32_t a;
    asm("{ .reg .u64 t; cvta.to.shared.u64 t, %1; cvt.u32.u64 %0, t; }" : "=r"(a) : "l"(p));
    return a;
}
#define CPA16(dst, src) \
    asm volatile("cp.async.cg.shared.global [%0], [%1], 16;" :: "r"(dst), "l"(src))
#define CPA_COMMIT() asm volatile("cp.async.commit_group;" ::: "memory")
#define LDM_X4(r0, r1, r2, r3, addr) \
    asm volatile("ldmatrix.sync.aligned.m8n8.x4.shared.b16 {%0,%1,%2,%3}, [%4];" \
                 : "=r"(r0), "=r"(r1), "=r"(r2), "=r"(r3) : "r"(addr))

// ---------------- block LN statistics over 256 threads ----------------
__device__ __forceinline__ void block_stats256(float val, float& mean, float& rstd) {
    float s = val, sq = val * val;
    #pragma unroll
    for (int o = 16; o; o >>= 1) {
        s  += __shfl_xor_sync(0xffffffffu, s,  o);
        sq += __shfl_xor_sync(0xffffffffu, sq, o);
    }
    __shared__ float ss[8], sqq[8];
    int lane = threadIdx.x & 31, w = threadIdx.x >> 5;
    if (lane == 0) { ss[w] = s; sqq[w] = sq; }
    __syncthreads();
    if (w == 0) {
        s  = (lane < 8) ? ss[lane]  : 0.f;
        sq = (lane < 8) ? sqq[lane] : 0.f;
        #pragma unroll
        for (int o = 4; o; o >>= 1) {
            s  += __shfl_xor_sync(0xffffffffu, s,  o);
            sq += __shfl_xor_sync(0xffffffffu, sq, o);
        }
        if (lane == 0) { ss[0] = s; sqq[0] = sq; }
    }
    __syncthreads();
    s = ss[0]; sq = sqq[0];
    mean = s * (1.f / 256.f);
    float var = sq * (1.f / 256.f) - mean * mean;
    rstd = rsqrtf(var + EPS);
}

// ---------------- context MLP ----------------
__global__ void ctx_kernel(const float* __restrict__ cc, const float* __restrict__ W,
                           const float* __restrict__ bias, const float* __restrict__ lns,
                           const float* __restrict__ lnb) {
    int b = blockIdx.x, d = threadIdx.x;
    __shared__ float cs[CSE];
    if (d < CSE) cs[d] = cc[b*CSE + d];
    __syncthreads();
    float acc = bias[d];
    #pragma unroll 4
    for (int k = 0; k < CSE; k++) acc += cs[k] * W[k*HD + d];
    float mean, rstd;
    block_stats256(acc, mean, rstd);
    float y = (acc - mean) * rstd * lns[d] + lnb[d];
    g_g[b*HD + d] = fmaxf(y, 0.f);
}

// ---------------- input embed ----------------
__global__ void embed_kernel(const float* __restrict__ so, const float* __restrict__ W,
                             const float* __restrict__ bias) {
    int bs = blockIdx.x; int b = bs / NS, s = bs % NS; int d = threadIdx.x;
    __shared__ float sv[NP];
    if (d < NP) sv[d] = so[(b*NP + d)*NS + s];
    __syncthreads();
    float acc = bias[d];
    #pragma unroll
    for (int p = 0; p < NP; p++) acc += sv[p] * W[p*HD + d];
    g_x[bs*HD + d] = acc;
}

// ---------------- c[l,b,:] = g[b] @ cp_W[l] + cp_b[l], ALL layers ----------------
__global__ void cp_all_kernel(const float* __restrict__ cp_W, const float* __restrict__ cp_b) {
    int b = blockIdx.x, l = blockIdx.y, d = threadIdx.x;
    __shared__ float gs[HD];
    gs[d] = g_g[b*HD + d];
    __syncthreads();
    const float* W = cp_W + (size_t)l*HD*HD;
    float acc = cp_b[l*HD + d];
    #pragma unroll 16
    for (int k = 0; k < HD; k++) acc += gs[k] * W[k*HD + d];
    g_c[(l*B + b)*HD + d] = acc;
}

// ---------------- h = LN(x)*s+b + c, split to bf16 hi/lo ----------------
__global__ void ln_add_kernel(const float* __restrict__ lns, const float* __restrict__ lnb, int l) {
    int bs = blockIdx.x, d = threadIdx.x; int b = bs / NS;
    float val = g_x[bs*HD + d];
    float mean, rstd;
    block_stats256(val, mean, rstd);
    float y = (val - mean) * rstd * lns[d] + lnb[d] + g_c[(l*B + b)*HD + d];
    __nv_bfloat16 hh = __float2bfloat16(y);
    g_Ahi[bs*HD + d] = hh;
    g_Alo[bs*HD + d] = __float2bfloat16(y - __bfloat162float(hh));
}

// ---------------- all-layer weight transpose + bf16 split (tiled) ----------------
__global__ void convW_all(const float* __restrict__ Wl, const float* __restrict__ Wr,
                          const float* __restrict__ Wo) {
    __shared__ float t[32][33];
    int m = blockIdx.z; int l = m / 3, sel = m - l*3;
    const float* src = (sel == 0 ? Wl : sel == 1 ? Wr : Wo) + (size_t)l*HD*HD;
    int k0 = blockIdx.x*32, n0 = blockIdx.y*32;
    int x = threadIdx.x, y = threadIdx.y;
    #pragma unroll
    for (int yy = y; yy < 32; yy += 8)
        t[yy][x] = src[(size_t)(k0 + yy)*HD + n0 + x];
    __syncthreads();
    int drow0 = l*768 + sel*256 + n0;
    #pragma unroll
    for (int yy = y; yy < 32; yy += 8) {
        float v = t[x][yy];
        __nv_bfloat16 hh = __float2bfloat16(v);
        size_t idx = (size_t)(drow0 + yy)*HD + k0 + x;
        g_Bhi[idx] = hh;
        g_Blo[idx] = __float2bfloat16(v - __bfloat162float(hh));
    }
}

// ---------------- mma.sync bf16 GEMM: ldmatrix + cp.async double buffer ----------------
// C[4608, Ntot] = A[4608,256] @ B^T, 3-term split AhBh+AhBl+AlBh, fp32 accum.
// MODE 0: A=(g_Ahi,g_Alo), C = g_hl (n<256)/g_hr.  grid (36, 8)
// MODE 1: A=(g_Ghi,g_Glo), C = g_x accumulate + bias.  grid (36, 4)
__device__ __forceinline__ void mma_bf16(float* c, const uint32_t* a, const uint32_t* b) {
    asm volatile(
        "mma.sync.aligned.m16n8k16.row.col.f32.bf16.bf16.f32 "
        "{%0,%1,%2,%3}, {%4,%5,%6,%7}, {%8,%9}, {%0,%1,%2,%3};"
        : "+f"(c[0]), "+f"(c[1]), "+f"(c[2]), "+f"(c[3])
        : "r"(a[0]), "r"(a[1]), "r"(a[2]), "r"(a[3]), "r"(b[0]), "r"(b[1]));
}
// per-stage layout: sAh 0 | sAl 16384 | sBh 32768 | sBl 40960 ; stage span 49152
#define GSTAGE 49152
#define GSM_TOTAL (2*GSTAGE)

template<int MODE>
__global__ void __launch_bounds__(256) gemm_mma(int wrow, const float* __restrict__ bias) {
    extern __shared__ char smc[];
    const __nv_bfloat16* Ahi = (MODE == 0) ? g_Ahi : g_Ghi;
    const __nv_bfloat16* Alo = (MODE == 0) ? g_Alo : g_Glo;
    uint32_t sbase = smem_u32(smc);
    int tid = threadIdx.x, lane = tid & 31, warp = tid >> 5;
    int wm = warp >> 1, wn = warp & 1;
    int m0   = blockIdx.x * 128;
    int nloc = blockIdx.y * 64;
    const __nv_bfloat16* Bhi = g_Bhi + (size_t)(wrow + nloc) * HD;
    const __nv_bfloat16* Blo = g_Blo + (size_t)(wrow + nloc) * HD;
    int lr = lane >> 2, lc2 = (lane & 3) * 2;

    int arow = tid >> 1, ahalf = tid & 1;     // A: 2 thr/row, 64B each
    int brow = tid >> 2, bq = tid & 3;        // B: 4 thr/row, 32B each

    auto load_stage = [&](int kc, int buf) {
        uint32_t sb = sbase + buf * GSTAGE;
        const char* gAh = (const char*)(Ahi + (size_t)(m0 + arow)*HD + kc*64) + ahalf*64;
        const char* gAl = (const char*)(Alo + (size_t)(m0 + arow)*HD + kc*64) + ahalf*64;
        #pragma unroll
        for (int c = 0; c < 4; c++) {
            uint32_t sw = SWZ128((uint32_t)(arow*128 + ahalf*64 + c*16));
            CPA16(sb + sw, gAh + c*16);
            CPA16(sb + 16384 + sw, gAl + c*16);
        }
        const char* gBh = (const char*)(Bhi + (size_t)brow*HD + kc*64) + bq*32;
        const char* gBl = (const char*)(Blo + (size_t)brow*HD + kc*64) + bq*32;
        #pragma unroll
        for (int c = 0; c < 2; c++) {
            uint32_t sw = SWZ128((uint32_t)(brow*128 + bq*32 + c*16));
            CPA16(sb + 32768 + sw, gBh + c*16);
            CPA16(sb + 40960 + sw, gBl + c*16);
        }
        CPA_COMMIT();
    };

    float acc[2][4][4];
    #pragma unroll
    for (int mt = 0; mt < 2; mt++)
        #pragma unroll
        for (int nt = 0; nt < 4; nt++)
            #pragma unroll
            for (int c = 0; c < 4; c++) acc[mt][nt][c] = 0.f;

    load_stage(0, 0);
    load_stage(1, 1);

    int sub = lane >> 3, lrow = lane & 7;

    for (int kc = 0; kc < 4; kc++) {
        if (kc == 3) asm volatile("cp.async.wait_group 0;" ::: "memory");
        else         asm volatile("cp.async.wait_group 1;" ::: "memory");
        __syncthreads();
        uint32_t sb = sbase + (kc & 1) * GSTAGE;

        #pragma unroll
        for (int ks = 0; ks < 4; ks++) {
            uint32_t ah[2][4], al[2][4], bh[4][2], bl[4][2];
            // A fragments: per mt one ldmatrix.x4 (matrices m0k0, m8k0, m0k8, m8k8)
            #pragma unroll
            for (int mt = 0; mt < 2; mt++) {
                int ar = wm*32 + mt*16 + (sub & 1)*8 + lrow;
                int ac = ks*32 + (sub >> 1)*16;                 // byte offset in 128B row
                uint32_t off = SWZ128((uint32_t)(ar*128 + ac));
                LDM_X4(ah[mt][0], ah[mt][1], ah[mt][2], ah[mt][3], sb + off);
                LDM_X4(al[mt][0], al[mt][1], al[mt][2], al[mt][3], sb + 16384 + off);
            }
            // B fragments: per nt-pair one ldmatrix.x4 (nt0k0, nt0k8, nt1k0, nt1k8)
            #pragma unroll
            for (int pair = 0; pair < 2; pair++) {
                int ntb = sub >> 1, khalf = sub & 1;
                int br = wn*32 + pair*16 + ntb*8 + lrow;
                int bc = ks*32 + khalf*16;
                uint32_t off = SWZ128((uint32_t)(br*128 + bc));
                LDM_X4(bh[2*pair][0], bh[2*pair][1], bh[2*pair+1][0], bh[2*pair+1][1],
                       sb + 32768 + off);
                LDM_X4(bl[2*pair][0], bl[2*pair][1], bl[2*pair+1][0], bl[2*pair+1][1],
                       sb + 40960 + off);
            }
            #pragma unroll
            for (int mt = 0; mt < 2; mt++)
                #pragma unroll
                for (int nt = 0; nt < 4; nt++) {
                    mma_bf16(acc[mt][nt], ah[mt], bh[nt]);
                    mma_bf16(acc[mt][nt], ah[mt], bl[nt]);
                    mma_bf16(acc[mt][nt], al[mt], bh[nt]);
                }
        }
        __syncthreads();
        if (kc < 2) load_stage(kc + 2, kc & 1);
    }

    #pragma unroll
    for (int mt = 0; mt < 2; mt++) {
        int r = m0 + wm*32 + mt*16 + lr;
        #pragma unroll
        for (int nt = 0; nt < 4; nt++) {
            int gn = nloc + wn*32 + nt*8 + lc2;
            if (MODE == 0) {
                float* C = (gn < 256) ? g_hl : g_hr;
                int cc = gn & 255;
                C[(size_t)r*HD + cc]           = acc[mt][nt][0];
                C[(size_t)r*HD + cc + 1]       = acc[mt][nt][1];
                C[(size_t)(r+8)*HD + cc]       = acc[mt][nt][2];
                C[(size_t)(r+8)*HD + cc + 1]   = acc[mt][nt][3];
            } else {
                g_x[(size_t)r*HD + gn]         += acc[mt][nt][0] + bias[gn];
                g_x[(size_t)r*HD + gn + 1]     += acc[mt][nt][1] + bias[gn + 1];
                g_x[(size_t)(r+8)*HD + gn]     += acc[mt][nt][2] + bias[gn];
                g_x[(size_t)(r+8)*HD + gn + 1] += acc[mt][nt][3] + bias[gn + 1];
            }
        }
    }
}

// ---------------- GATv2 attention, parallel over (batch, i-chunk) ----------------
#define TI 8
#define ATTN_SMEM ((NS*HD + TI*HD + TI*NS*H + TI*NS) * sizeof(float))
__global__ void attn_kernel(const float* __restrict__ adj, const float* __restrict__ Wa) {
    int b = blockIdx.x;
    int i0 = blockIdx.y * TI;
    int tid = threadIdx.x, lane = tid & 31, warp = tid >> 5;
    extern __shared__ float smf[];
    float* hrs  = smf;
    float* hls  = hrs + NS*HD;
    float* sc   = hls + TI*HD;
    float* adjr = sc + TI*NS*H;
    __shared__ float wa_s[H*F];
    wa_s[tid] = Wa[tid];
    const float* src_r = g_hr + b*NS*HD;
    const float* src_l = g_hl + (b*NS + i0)*HD;
    for (int k = tid; k < NS*HD; k += 256) hrs[k] = src_r[k];
    for (int k = tid; k < TI*HD; k += 256) hls[k] = src_l[k];
    for (int k = tid; k < TI*NS; k += 256) adjr[k] = adj[(i0 + k/NS)*NS + (k % NS)];
    __syncthreads();

    for (int e = warp; e < TI*NS*H; e += 8) {
        int i = e / (NS*H);
        int rem = e - i*(NS*H);
        int j = rem / H, h = rem - j*H;
        float p = 0.f;
        #pragma unroll
        for (int fc = 0; fc < F; fc += 32) {
            int f = fc + lane;
            float v = hls[i*HD + h*F + f] + hrs[j*HD + h*F + f];
            v = (v > 0.f) ? v : 0.2f * v;
            p += wa_s[h*F + f] * v;
        }
        #pragma unroll
        for (int o = 16; o; o >>= 1) p += __shfl_xor_sync(0xffffffffu, p, o);
        if (lane == 0) sc[(i*NS + j)*H + h] = (adjr[i*NS + j] > 0.f) ? p : -1e9f;
    }
    __syncthreads();

    for (int p = warp; p < TI*H; p += 8) {
        int i = p >> 2, h = p & 3;
        float m = -1e30f;
        for (int j = lane; j < NS; j += 32) m = fmaxf(m, sc[(i*NS + j)*H + h]);
        #pragma unroll
        for (int o = 16; o; o >>= 1) m = fmaxf(m, __shfl_xor_sync(0xffffffffu, m, o));
        float s = 0.f;
        for (int j = lane; j < NS; j += 32) {
            float e2 = expf(sc[(i*NS + j)*H + h] - m);
            sc[(i*NS + j)*H + h] = e2; s += e2;
        }
        #pragma unroll
        for (int o = 16; o; o >>= 1) s += __shfl_xor_sync(0xffffffffu, s, o);
        float inv = 1.f / s;
        for (int j = lane; j < NS; j += 32) sc[(i*NS + j)*H + h] *= inv;
    }
    __syncthreads();

    int d = tid, h = d >> 6;
    float acc[TI] = {};
    for (int j = 0; j < NS; j++) {
        float hv = hrs[j*HD + d];
        #pragma unroll
        for (int i = 0; i < TI; i++) acc[i] += sc[(i*NS + j)*H + h] * hv;
    }
    #pragma unroll
    for (int i = 0; i < TI; i++) {
        float v = acc[i];
        __nv_bfloat16 hh = __float2bfloat16(v);
        size_t idx = (size_t)(b*NS + i0 + i)*HD + d;
        g_Ghi[idx] = hh;
        g_Glo[idx] = __float2bfloat16(v - __bfloat162float(hh));
    }
}

// ---------------- mean pool over NS ----------------
__global__ void mean_kernel() {
    int b = blockIdx.x, d = threadIdx.x;
    float acc = 0.f;
    #pragma unroll 8
    for (int s = 0; s < NS; s++) acc += g_x[(b*NS + s)*HD + d];
    g_ge[b*HD + d] = acc * (1.f / (float)NS);
}

// ---------------- output heads ----------------
#define OUT_CARD 0
#define OUT_AT   (B*NC)
#define OUT_SRC  (OUT_AT + B*3)
#define OUT_TGT  (OUT_SRC + B*NS)
#define OUT_VAL  (OUT_TGT + B*NS)
__global__ void heads_kernel(const float* __restrict__ cW, const float* __restrict__ cb,
                             const float* __restrict__ aW, const float* __restrict__ ab,
                             const float* __restrict__ sW, const float* __restrict__ sb,
                             const float* __restrict__ tW, const float* __restrict__ tb,
                             const float* __restrict__ v1W, const float* __restrict__ v1b,
                             const float* __restrict__ v2W, const float* __restrict__ v2b,
                             float* __restrict__ out) {
    int b = blockIdx.x, tid = threadIdx.x;
    __shared__ float ge[HD];
    __shared__ float vh[128];
    __shared__ float vpart[4];
    ge[tid] = g_ge[b*HD + tid];
    __syncthreads();
    if (tid < NC) {
        float a = cb[tid];
        for (int k = 0; k < HD; k++) a += ge[k] * cW[k*NC + tid];
        out[OUT_CARD + b*NC + tid] = a;
    }
    if (tid < 3) {
        float a = ab[tid];
        for (int k = 0; k < HD; k++) a += ge[k] * aW[k*3 + tid];
        out[OUT_AT + b*3 + tid] = a;
    }
    if (tid < NS) {
        float a = sb[tid], t = tb[tid];
        for (int k = 0; k < HD; k++) { a += ge[k] * sW[k*NS + tid]; t += ge[k] * tW[k*NS + tid]; }
        out[OUT_SRC + b*NS + tid] = a;
        out[OUT_TGT + b*NS + tid] = t;
    }
    if (tid < 128) {
        float a = v1b[tid];
        for (int k = 0; k < HD; k++) a += ge[k] * v1W[k*128 + tid];
        vh[tid] = fmaxf(a, 0.f);
    }
    __syncthreads();
    if (tid < 128) {
        float p = vh[tid] * v2W[tid];
        #pragma unroll
        for (int o = 16; o; o >>= 1) p += __shfl_xor_sync(0xffffffffu, p, o);
        if ((tid & 31) == 0) vpart[tid >> 5] = p;
    }
    __syncthreads();
    if (tid == 0) {
        float s = vpart[0] + vpart[1] + vpart[2] + vpart[3] + v2b[0];
        out[OUT_VAL + b] = tanhf(s);
    }
}

// ---------------- launch ----------------
extern "C" void kernel_launch(void* const* d_in, const int* in_sizes, int n_in,
                              void* d_out, int out_size) {
    const float* spatial_obs = (const float*)d_in[0];
    const float* card_ctx    = (const float*)d_in[1];
    const float* adj         = (const float*)d_in[2];
    const float* ctx_W  = (const float*)d_in[3];
    const float* ctx_b  = (const float*)d_in[4];
    const float* lnc_s  = (const float*)d_in[5];
    const float* lnc_b  = (const float*)d_in[6];
    const float* in_W   = (const float*)d_in[7];
    const float* in_b   = (const float*)d_in[8];
    const float* lnp_s  = (const float*)d_in[9];
    const float* lnp_b  = (const float*)d_in[10];
    const float* cp_W   = (const float*)d_in[11];
    const float* cp_b   = (const float*)d_in[12];
    const float* Wl     = (const float*)d_in[13];
    const float* Wr     = (const float*)d_in[14];
    const float* Wa     = (const float*)d_in[15];
    const float* op_W   = (const float*)d_in[16];
    const float* op_b   = (const float*)d_in[17];
    const float* card_W = (const float*)d_in[18];
    const float* card_b = (const float*)d_in[19];
    const float* at_W   = (const float*)d_in[20];
    const float* at_b   = (const float*)d_in[21];
    const float* src_W  = (const float*)d_in[22];
    const float* src_b  = (const float*)d_in[23];
    const float* tgt_W  = (const float*)d_in[24];
    const float* tgt_b  = (const float*)d_in[25];
    const float* v1_W   = (const float*)d_in[26];
    const float* v1_b   = (const float*)d_in[27];
    const float* v2_W   = (const float*)d_in[28];
    const float* v2_b   = (const float*)d_in[29];
    float* out = (float*)d_out;

    cudaFuncSetAttribute(attn_kernel, cudaFuncAttributeMaxDynamicSharedMemorySize, ATTN_SMEM);
    cudaFuncSetAttribute(gemm_mma<0>, cudaFuncAttributeMaxDynamicSharedMemorySize, GSM_TOTAL);
    cudaFuncSetAttribute(gemm_mma<1>, cudaFuncAttributeMaxDynamicSharedMemorySize, GSM_TOTAL);

    ctx_kernel<<<B, HD>>>(card_ctx, ctx_W, ctx_b, lnc_s, lnc_b);
    embed_kernel<<<B*NS, HD>>>(spatial_obs, in_W, in_b);
    convW_all<<<dim3(8, 8, 12), dim3(32, 8)>>>(Wl, Wr, op_W);
    cp_all_kernel<<<dim3(B, L), HD>>>(cp_W, cp_b);

    dim3 agrid(B, NS/TI);
    dim3 glr(36, 8);   // fused Wl|Wr, Ntot=512
    dim3 gop(36, 4);   // op_W,       Ntot=256
    for (int l = 0; l < L; l++) {
        ln_add_kernel<<<B*NS, HD>>>(lnp_s + l*HD, lnp_b + l*HD, l);
        gemm_mma<0><<<glr, 256, GSM_TOTAL>>>(l*768, nullptr);
        attn_kernel<<<agrid, 256, ATTN_SMEM>>>(adj, Wa + l*H*F);
        gemm_mma<1><<<gop, 256, GSM_TOTAL>>>(l*768 + 512, op_b + l*HD);
    }

    mean_kernel<<<B, HD>>>();
    heads_kernel<<<B, HD>>>(card_W, card_b, at_W, at_b, src_W, src_b,
                            tgt_W, tgt_b, v1_W, v1_b, v2_W, v2_b, out);
}

// round 12
// speedup vs baseline: 4.7591x; 1.4844x over previous
#include <cuda_runtime.h>
#include <cuda_bf16.h>
#include <math.h>
#include <stdint.h>

#define B 64
#define NP 32
#define NS 72
#define HD 256
#define H 4
#define F 64
#define CSE 112
#define L 4
#define NC 110
#define EPS 1e-6f

// ---------------- device scratch (no allocations; device-code refs only) ----------------
__device__ float g_c [L*B*HD];
__device__ float g_x [B*NS*HD];
__device__ float g_hl[B*NS*HD];
__device__ float g_hr[B*NS*HD];
__device__ __nv_bfloat16 g_Ghi[B*NS*HD];
__device__ __nv_bfloat16 g_Glo[B*NS*HD];
// weights K-major [n][k]; per layer 768 rows (Wl 256 | Wr 256 | op 256)
__device__ __nv_bfloat16 g_Bhi[L*768*HD];
__device__ __nv_bfloat16 g_Blo[L*768*HD];

#define SWZ128(bo) ((bo) ^ (((bo) >> 3) & 0x70))

__device__ __forceinline__ uint32_t smem_u32(const void* p) {
    uint32_t a;
    asm("{ .reg .u64 t; cvta.to.shared.u64 t, %1; cvt.u32.u64 %0, t; }" : "=r"(a) : "l"(p));
    return a;
}
#define LDM_X4(r0, r1, r2, r3, addr) \
    asm volatile("ldmatrix.sync.aligned.m8n8.x4.shared.b16 {%0,%1,%2,%3}, [%4];" \
                 : "=r"(r0), "=r"(r1), "=r"(r2), "=r"(r3) : "r"(addr))
#define CPA16(dst, src) \
    asm volatile("cp.async.cg.shared.global [%0], [%1], 16;" :: "r"(dst), "l"(src))
#define CPA_COMMIT() asm volatile("cp.async.commit_group;" ::: "memory")

__device__ __forceinline__ void mma_bf16(float* c, const uint32_t* a, const uint32_t* b) {
    asm volatile(
        "mma.sync.aligned.m16n8k16.row.col.f32.bf16.bf16.f32 "
        "{%0,%1,%2,%3}, {%4,%5,%6,%7}, {%8,%9}, {%0,%1,%2,%3};"
        : "+f"(c[0]), "+f"(c[1]), "+f"(c[2]), "+f"(c[3])
        : "r"(a[0]), "r"(a[1]), "r"(a[2]), "r"(a[3]), "r"(b[0]), "r"(b[1]));
}
__device__ __forceinline__ uint32_t bf2u(__nv_bfloat162 v) {
    return *(uint32_t*)&v;
}

// ---------------- block LN statistics over 256 threads ----------------
__device__ __forceinline__ void block_stats256(float val, float& mean, float& rstd) {
    float s = val, sq = val * val;
    #pragma unroll
    for (int o = 16; o; o >>= 1) {
        s  += __shfl_xor_sync(0xffffffffu, s,  o);
        sq += __shfl_xor_sync(0xffffffffu, sq, o);
    }
    __shared__ float ss[8], sqq[8];
    int lane = threadIdx.x & 31, w = threadIdx.x >> 5;
    if (lane == 0) { ss[w] = s; sqq[w] = sq; }
    __syncthreads();
    if (w == 0) {
        s  = (lane < 8) ? ss[lane]  : 0.f;
        sq = (lane < 8) ? sqq[lane] : 0.f;
        #pragma unroll
        for (int o = 4; o; o >>= 1) {
            s  += __shfl_xor_sync(0xffffffffu, s,  o);
            sq += __shfl_xor_sync(0xffffffffu, sq, o);
        }
        if (lane == 0) { ss[0] = s; sqq[0] = sq; }
    }
    __syncthreads();
    s = ss[0]; sq = sqq[0];
    mean = s * (1.f / 256.f);
    float var = sq * (1.f / 256.f) - mean * mean;
    rstd = rsqrtf(var + EPS);
}

// ---------------- fused prep: embed | convW | ctx+cp  (blockIdx dispatch) ----------------
__global__ void prep_kernel(
    const float* __restrict__ so, const float* __restrict__ in_W, const float* __restrict__ in_b,
    const float* __restrict__ cc, const float* __restrict__ ctx_W, const float* __restrict__ ctx_b,
    const float* __restrict__ lnc_s, const float* __restrict__ lnc_b,
    const float* __restrict__ cp_W, const float* __restrict__ cp_b,
    const float* __restrict__ Wl, const float* __restrict__ Wr, const float* __restrict__ Wo) {
    int bid = blockIdx.x, tid = threadIdx.x;
    __shared__ float sv[NP];
    __shared__ float t[32][33];
    __shared__ float cs[CSE];
    __shared__ float gs[HD];
    if (bid < B*NS) {
        // ---- embed ----
        int b = bid / NS, s = bid - b*NS;
        if (tid < NP) sv[tid] = so[(b*NP + tid)*NS + s];
        __syncthreads();
        float acc = in_b[tid];
        #pragma unroll
        for (int p = 0; p < NP; p++) acc += sv[p] * in_W[p*HD + tid];
        g_x[bid*HD + tid] = acc;
    } else if (bid < B*NS + 768) {
        // ---- weight transpose + bf16 split ----
        int idx = bid - B*NS;
        int kt = idx & 7, nt = (idx >> 3) & 7, m = idx >> 6;
        int l = m / 3, sel = m - l*3;
        const float* src = (sel == 0 ? Wl : sel == 1 ? Wr : Wo) + (size_t)l*HD*HD;
        int k0 = kt*32, n0 = nt*32;
        int x = tid & 31, y = tid >> 5;
        #pragma unroll
        for (int yy = y; yy < 32; yy += 8)
            t[yy][x] = src[(size_t)(k0 + yy)*HD + n0 + x];
        __syncthreads();
        int drow0 = l*768 + sel*256 + n0;
        #pragma unroll
        for (int yy = y; yy < 32; yy += 8) {
            float v = t[x][yy];
            __nv_bfloat16 hh = __float2bfloat16(v);
            size_t di = (size_t)(drow0 + yy)*HD + k0 + x;
            g_Bhi[di] = hh;
            g_Blo[di] = __float2bfloat16(v - __bfloat162float(hh));
        }
    } else {
        // ---- ctx (recomputed per layer) + cp ----
        int idx = bid - (B*NS + 768);
        int b = idx & 63, l = idx >> 6;
        if (tid < CSE) cs[tid] = cc[b*CSE + tid];
        __syncthreads();
        float acc = ctx_b[tid];
        #pragma unroll 4
        for (int k = 0; k < CSE; k++) acc += cs[k] * ctx_W[k*HD + tid];
        float mean, rstd;
        block_stats256(acc, mean, rstd);
        gs[tid] = fmaxf((acc - mean)*rstd*lnc_s[tid] + lnc_b[tid], 0.f);
        __syncthreads();
        const float* W = cp_W + (size_t)l*HD*HD;
        float a2 = cp_b[l*HD + tid];
        #pragma unroll 16
        for (int k = 0; k < HD; k++) a2 += gs[k] * W[k*HD + tid];
        g_c[(l*B + b)*HD + tid] = a2;
    }
}

// ---------------- gemm0 with fused LayerNorm prologue ----------------
// C[4608,512] = LN(g_x)+c  @  [Wl|Wr]^T.   grid (36, 8), 256 thr.
#define G0_AH 0
#define G0_AL 16384
#define G0_BH 32768
#define G0_BL 40960
#define G0_ST 49152
#define G0_TOTAL (49152 + 128*2*4)
__global__ void __launch_bounds__(256) gemm0ln(int l, const float* __restrict__ lns,
                                               const float* __restrict__ lnb) {
    extern __shared__ char smc[];
    uint32_t sbase = smem_u32(smc);
    float* stats = (float*)(smc + G0_ST);
    int tid = threadIdx.x, lane = tid & 31, warp = tid >> 5;
    int wm = warp >> 1, wn = warp & 1;
    int m0 = blockIdx.x * 128, nloc = blockIdx.y * 64;
    const __nv_bfloat16* Bhi = g_Bhi + (size_t)(l*768 + nloc) * HD;
    const __nv_bfloat16* Blo = g_Blo + (size_t)(l*768 + nloc) * HD;

    // pass1: row mean/rstd, 2 threads per row
    int row = tid >> 1, half = tid & 1;
    {
        const float4* xr = (const float4*)(g_x + (size_t)(m0 + row)*HD + half*128);
        float s = 0.f, sq = 0.f;
        #pragma unroll
        for (int c = 0; c < 32; c++) {
            float4 v = xr[c];
            s  += v.x + v.y + v.z + v.w;
            sq += v.x*v.x + v.y*v.y + v.z*v.z + v.w*v.w;
        }
        s  += __shfl_xor_sync(0xffffffffu, s, 1);
        sq += __shfl_xor_sync(0xffffffffu, sq, 1);
        if (half == 0) {
            float mean = s * (1.f/256.f);
            float var  = sq * (1.f/256.f) - mean*mean;
            stats[row*2]     = mean;
            stats[row*2 + 1] = rsqrtf(var + EPS);
        }
    }
    __syncthreads();

    int bidx = (m0 + row) / NS;
    const float* crow = g_c + (size_t)(l*B + bidx)*HD;
    int brow = tid >> 2, bq = tid & 3;
    int sub = lane >> 3, lrow = lane & 7;
    int lr = lane >> 2, lc2 = (lane & 3) * 2;

    float acc[2][4][4];
    #pragma unroll
    for (int mt = 0; mt < 2; mt++)
        #pragma unroll
        for (int nt = 0; nt < 4; nt++)
            #pragma unroll
            for (int c = 0; c < 4; c++) acc[mt][nt][c] = 0.f;

    for (int kc = 0; kc < 4; kc++) {
        if (kc) __syncthreads();
        // stage A with LN transform + bf16 split
        {
            float mean = stats[row*2], rstd = stats[row*2 + 1];
            int colbase = kc*64 + half*32;
            const float4* src = (const float4*)(g_x + (size_t)(m0 + row)*HD + colbase);
            const float4* ls4 = (const float4*)(lns + colbase);
            const float4* lb4 = (const float4*)(lnb + colbase);
            const float4* cr4 = (const float4*)(crow + colbase);
            #pragma unroll
            for (int c = 0; c < 8; c++) {
                float4 v = src[c], sg = ls4[c], bt = lb4[c], cv = cr4[c];
                float y0 = (v.x - mean)*rstd*sg.x + bt.x + cv.x;
                float y1 = (v.y - mean)*rstd*sg.y + bt.y + cv.y;
                float y2 = (v.z - mean)*rstd*sg.z + bt.z + cv.z;
                float y3 = (v.w - mean)*rstd*sg.w + bt.w + cv.w;
                __nv_bfloat162 h01 = __floats2bfloat162_rn(y0, y1);
                __nv_bfloat162 h23 = __floats2bfloat162_rn(y2, y3);
                __nv_bfloat162 l01 = __floats2bfloat162_rn(y0 - __bfloat162float(h01.x),
                                                           y1 - __bfloat162float(h01.y));
                __nv_bfloat162 l23 = __floats2bfloat162_rn(y2 - __bfloat162float(h23.x),
                                                           y3 - __bfloat162float(h23.y));
                uint32_t bo = (uint32_t)(row*128 + half*64 + c*8);
                uint32_t sw = SWZ128(bo);
                *(uint2*)(smc + G0_AH + sw) = make_uint2(bf2u(h01), bf2u(h23));
                *(uint2*)(smc + G0_AL + sw) = make_uint2(bf2u(l01), bf2u(l23));
            }
        }
        // stage B (plain vector loads)
        {
            const uint4* bh4 = (const uint4*)((const char*)(Bhi + (size_t)brow*HD + kc*64) + bq*32);
            const uint4* bl4 = (const uint4*)((const char*)(Blo + (size_t)brow*HD + kc*64) + bq*32);
            #pragma unroll
            for (int c = 0; c < 2; c++) {
                uint32_t sw = SWZ128((uint32_t)(brow*128 + bq*32 + c*16));
                *(uint4*)(smc + G0_BH + sw) = bh4[c];
                *(uint4*)(smc + G0_BL + sw) = bl4[c];
            }
        }
        __syncthreads();
        #pragma unroll
        for (int ks = 0; ks < 4; ks++) {
            uint32_t ah[2][4], al[2][4], bh[4][2], bl[4][2];
            #pragma unroll
            for (int mt = 0; mt < 2; mt++) {
                int ar = wm*32 + mt*16 + (sub & 1)*8 + lrow;
                int ac = ks*32 + (sub >> 1)*16;
                uint32_t off = SWZ128((uint32_t)(ar*128 + ac));
                LDM_X4(ah[mt][0], ah[mt][1], ah[mt][2], ah[mt][3], sbase + G0_AH + off);
                LDM_X4(al[mt][0], al[mt][1], al[mt][2], al[mt][3], sbase + G0_AL + off);
            }
            #pragma unroll
            for (int pair = 0; pair < 2; pair++) {
                int ntb = sub >> 1, khalf = sub & 1;
                int br = wn*32 + pair*16 + ntb*8 + lrow;
                int bc = ks*32 + khalf*16;
                uint32_t off = SWZ128((uint32_t)(br*128 + bc));
                LDM_X4(bh[2*pair][0], bh[2*pair][1], bh[2*pair+1][0], bh[2*pair+1][1],
                       sbase + G0_BH + off);
                LDM_X4(bl[2*pair][0], bl[2*pair][1], bl[2*pair+1][0], bl[2*pair+1][1],
                       sbase + G0_BL + off);
            }
            #pragma unroll
            for (int mt = 0; mt < 2; mt++)
                #pragma unroll
                for (int nt = 0; nt < 4; nt++) {
                    mma_bf16(acc[mt][nt], ah[mt], bh[nt]);
                    mma_bf16(acc[mt][nt], ah[mt], bl[nt]);
                    mma_bf16(acc[mt][nt], al[mt], bh[nt]);
                }
        }
    }

    #pragma unroll
    for (int mt = 0; mt < 2; mt++) {
        int r = m0 + wm*32 + mt*16 + lr;
        #pragma unroll
        for (int nt = 0; nt < 4; nt++) {
            int gn = nloc + wn*32 + nt*8 + lc2;
            float* C = (gn < 256) ? g_hl : g_hr;
            int cc2 = gn & 255;
            C[(size_t)r*HD + cc2]         = acc[mt][nt][0];
            C[(size_t)r*HD + cc2 + 1]     = acc[mt][nt][1];
            C[(size_t)(r+8)*HD + cc2]     = acc[mt][nt][2];
            C[(size_t)(r+8)*HD + cc2 + 1] = acc[mt][nt][3];
        }
    }
}

// ---------------- gemm1: g_x += (G @ opW^T) + bias ; cp.async double buffer ----------------
#define GSTAGE 49152
#define GSM_TOTAL (2*GSTAGE)
__global__ void __launch_bounds__(256) gemm1_mma(int wrow, const float* __restrict__ bias) {
    extern __shared__ char smc[];
    uint32_t sbase = smem_u32(smc);
    int tid = threadIdx.x, lane = tid & 31, warp = tid >> 5;
    int wm = warp >> 1, wn = warp & 1;
    int m0   = blockIdx.x * 128;
    int nloc = blockIdx.y * 64;
    const __nv_bfloat16* Bhi = g_Bhi + (size_t)(wrow + nloc) * HD;
    const __nv_bfloat16* Blo = g_Blo + (size_t)(wrow + nloc) * HD;
    int lr = lane >> 2, lc2 = (lane & 3) * 2;
    int arow = tid >> 1, ahalf = tid & 1;
    int brow = tid >> 2, bq = tid & 3;

    auto load_stage = [&](int kc, int buf) {
        uint32_t sb = sbase + buf * GSTAGE;
        const char* gAh = (const char*)(g_Ghi + (size_t)(m0 + arow)*HD + kc*64) + ahalf*64;
        const char* gAl = (const char*)(g_Glo + (size_t)(m0 + arow)*HD + kc*64) + ahalf*64;
        #pragma unroll
        for (int c = 0; c < 4; c++) {
            uint32_t sw = SWZ128((uint32_t)(arow*128 + ahalf*64 + c*16));
            CPA16(sb + sw, gAh + c*16);
            CPA16(sb + 16384 + sw, gAl + c*16);
        }
        const char* gBh = (const char*)(Bhi + (size_t)brow*HD + kc*64) + bq*32;
        const char* gBl = (const char*)(Blo + (size_t)brow*HD + kc*64) + bq*32;
        #pragma unroll
        for (int c = 0; c < 2; c++) {
            uint32_t sw = SWZ128((uint32_t)(brow*128 + bq*32 + c*16));
            CPA16(sb + 32768 + sw, gBh + c*16);
            CPA16(sb + 40960 + sw, gBl + c*16);
        }
        CPA_COMMIT();
    };

    float acc[2][4][4];
    #pragma unroll
    for (int mt = 0; mt < 2; mt++)
        #pragma unroll
        for (int nt = 0; nt < 4; nt++)
            #pragma unroll
            for (int c = 0; c < 4; c++) acc[mt][nt][c] = 0.f;

    load_stage(0, 0);
    load_stage(1, 1);
    int sub = lane >> 3, lrow = lane & 7;

    for (int kc = 0; kc < 4; kc++) {
        if (kc == 3) asm volatile("cp.async.wait_group 0;" ::: "memory");
        else         asm volatile("cp.async.wait_group 1;" ::: "memory");
        __syncthreads();
        uint32_t sb = sbase + (kc & 1) * GSTAGE;
        #pragma unroll
        for (int ks = 0; ks < 4; ks++) {
            uint32_t ah[2][4], al[2][4], bh[4][2], bl[4][2];
            #pragma unroll
            for (int mt = 0; mt < 2; mt++) {
                int ar = wm*32 + mt*16 + (sub & 1)*8 + lrow;
                int ac = ks*32 + (sub >> 1)*16;
                uint32_t off = SWZ128((uint32_t)(ar*128 + ac));
                LDM_X4(ah[mt][0], ah[mt][1], ah[mt][2], ah[mt][3], sb + off);
                LDM_X4(al[mt][0], al[mt][1], al[mt][2], al[mt][3], sb + 16384 + off);
            }
            #pragma unroll
            for (int pair = 0; pair < 2; pair++) {
                int ntb = sub >> 1, khalf = sub & 1;
                int br = wn*32 + pair*16 + ntb*8 + lrow;
                int bc = ks*32 + khalf*16;
                uint32_t off = SWZ128((uint32_t)(br*128 + bc));
                LDM_X4(bh[2*pair][0], bh[2*pair][1], bh[2*pair+1][0], bh[2*pair+1][1],
                       sb + 32768 + off);
                LDM_X4(bl[2*pair][0], bl[2*pair][1], bl[2*pair+1][0], bl[2*pair+1][1],
                       sb + 40960 + off);
            }
            #pragma unroll
            for (int mt = 0; mt < 2; mt++)
                #pragma unroll
                for (int nt = 0; nt < 4; nt++) {
                    mma_bf16(acc[mt][nt], ah[mt], bh[nt]);
                    mma_bf16(acc[mt][nt], ah[mt], bl[nt]);
                    mma_bf16(acc[mt][nt], al[mt], bh[nt]);
                }
        }
        __syncthreads();
        if (kc < 2) load_stage(kc + 2, kc & 1);
    }

    #pragma unroll
    for (int mt = 0; mt < 2; mt++) {
        int r = m0 + wm*32 + mt*16 + lr;
        #pragma unroll
        for (int nt = 0; nt < 4; nt++) {
            int gn = nloc + wn*32 + nt*8 + lc2;
            g_x[(size_t)r*HD + gn]         += acc[mt][nt][0] + bias[gn];
            g_x[(size_t)r*HD + gn + 1]     += acc[mt][nt][1] + bias[gn + 1];
            g_x[(size_t)(r+8)*HD + gn]     += acc[mt][nt][2] + bias[gn];
            g_x[(size_t)(r+8)*HD + gn + 1] += acc[mt][nt][3] + bias[gn + 1];
        }
    }
}

// ---------------- GATv2 attention: thread-per-entry scores, TI=12 ----------------
#define TI 12
#define ATTN_SMEM ((NS*HD + TI*HD + TI*NS*H + TI*NS) * sizeof(float))
__global__ void attn_kernel(const float* __restrict__ adj, const float* __restrict__ Wa) {
    int b = blockIdx.x;
    int i0 = blockIdx.y * TI;
    int tid = threadIdx.x, lane = tid & 31, warp = tid >> 5;
    extern __shared__ float smf[];
    float* hrs  = smf;
    float* hls  = hrs + NS*HD;
    float* sc   = hls + TI*HD;
    float* adjr = sc + TI*NS*H;
    __shared__ float wa_s[H*F];
    wa_s[tid] = Wa[tid];
    {
        const float4* sr = (const float4*)(g_hr + (size_t)b*NS*HD);
        float4* dr = (float4*)hrs;
        for (int k = tid; k < NS*HD/4; k += 256) dr[k] = sr[k];
        const float4* sl = (const float4*)(g_hl + (size_t)(b*NS + i0)*HD);
        float4* dl = (float4*)hls;
        for (int k = tid; k < TI*HD/4; k += 256) dl[k] = sl[k];
        for (int k = tid; k < TI*NS; k += 256) adjr[k] = adj[(i0 + k/NS)*NS + (k % NS)];
    }
    __syncthreads();

    // scores: thread per (i,j,h) entry, serial f-loop, lane-skewed start
    for (int e = tid; e < TI*NS*H; e += 256) {
        int i = e / (NS*H);
        int rem = e - i*(NS*H);
        int j = rem >> 2, h = rem & 3;
        float outv = -1e9f;
        if (adjr[i*NS + j] > 0.f) {
            const float* pl = hls + i*HD + h*F;
            const float* pr = hrs + j*HD + h*F;
            const float* pw = wa_s + h*F;
            float p = 0.f;
            int f = lane;
            #pragma unroll 8
            for (int ff = 0; ff < F; ff++) {
                float v = pl[f] + pr[f];
                v = (v > 0.f) ? v : 0.2f * v;
                p = fmaf(pw[f], v, p);
                f = (f + 1) & 63;
            }
            outv = p;
        }
        sc[(i*NS + j)*H + h] = outv;
    }
    __syncthreads();

    // softmax over j: TI*H = 48 pairs, warp per pair
    for (int p = warp; p < TI*H; p += 8) {
        int i = p >> 2, h = p & 3;
        float m = -1e30f;
        for (int j = lane; j < NS; j += 32) m = fmaxf(m, sc[(i*NS + j)*H + h]);
        #pragma unroll
        for (int o = 16; o; o >>= 1) m = fmaxf(m, __shfl_xor_sync(0xffffffffu, m, o));
        float s = 0.f;
        for (int j = lane; j < NS; j += 32) {
            float e2 = expf(sc[(i*NS + j)*H + h] - m);
            sc[(i*NS + j)*H + h] = e2; s += e2;
        }
        #pragma unroll
        for (int o = 16; o; o >>= 1) s += __shfl_xor_sync(0xffffffffu, s, o);
        float inv = 1.f / s;
        for (int j = lane; j < NS; j += 32) sc[(i*NS + j)*H + h] *= inv;
    }
    __syncthreads();

    // output: thread owns column d; j outer
    int d = tid, h = d >> 6;
    float acc[TI] = {};
    for (int j = 0; j < NS; j++) {
        float hv = hrs[j*HD + d];
        #pragma unroll
        for (int i = 0; i < TI; i++) acc[i] += sc[(i*NS + j)*H + h] * hv;
    }
    #pragma unroll
    for (int i = 0; i < TI; i++) {
        float v = acc[i];
        __nv_bfloat16 hh = __float2bfloat16(v);
        size_t idx = (size_t)(b*NS + i0 + i)*HD + d;
        g_Ghi[idx] = hh;
        g_Glo[idx] = __float2bfloat16(v - __bfloat162float(hh));
    }
}

// ---------------- output heads (mean fused) ----------------
#define OUT_CARD 0
#define OUT_AT   (B*NC)
#define OUT_SRC  (OUT_AT + B*3)
#define OUT_TGT  (OUT_SRC + B*NS)
#define OUT_VAL  (OUT_TGT + B*NS)
__global__ void heads_kernel(const float* __restrict__ cW, const float* __restrict__ cb,
                             const float* __restrict__ aW, const float* __restrict__ ab,
                             const float* __restrict__ sW, const float* __restrict__ sb,
                             const float* __restrict__ tW, const float* __restrict__ tb,
                             const float* __restrict__ v1W, const float* __restrict__ v1b,
                             const float* __restrict__ v2W, const float* __restrict__ v2b,
                             float* __restrict__ out) {
    int b = blockIdx.x, tid = threadIdx.x;
    __shared__ float ge[HD];
    __shared__ float vh[128];
    __shared__ float vpart[4];
    {
        float m = 0.f;
        #pragma unroll 8
        for (int s = 0; s < NS; s++) m += g_x[(size_t)(b*NS + s)*HD + tid];
        ge[tid] = m * (1.f / (float)NS);
    }
    __syncthreads();
    if (tid < NC) {
        float a = cb[tid];
        for (int k = 0; k < HD; k++) a += ge[k] * cW[k*NC + tid];
        out[OUT_CARD + b*NC + tid] = a;
    }
    if (tid < 3) {
        float a = ab[tid];
        for (int k = 0; k < HD; k++) a += ge[k] * aW[k*3 + tid];
        out[OUT_AT + b*3 + tid] = a;
    }
    if (tid < NS) {
        float a = sb[tid], t = tb[tid];
        for (int k = 0; k < HD; k++) { a += ge[k] * sW[k*NS + tid]; t += ge[k] * tW[k*NS + tid]; }
        out[OUT_SRC + b*NS + tid] = a;
        out[OUT_TGT + b*NS + tid] = t;
    }
    if (tid < 128) {
        float a = v1b[tid];
        for (int k = 0; k < HD; k++) a += ge[k] * v1W[k*128 + tid];
        vh[tid] = fmaxf(a, 0.f);
    }
    __syncthreads();
    if (tid < 128) {
        float p = vh[tid] * v2W[tid];
        #pragma unroll
        for (int o = 16; o; o >>= 1) p += __shfl_xor_sync(0xffffffffu, p, o);
        if ((tid & 31) == 0) vpart[tid >> 5] = p;
    }
    __syncthreads();
    if (tid == 0) {
        float s = vpart[0] + vpart[1] + vpart[2] + vpart[3] + v2b[0];
        out[OUT_VAL + b] = tanhf(s);
    }
}

// ---------------- launch ----------------
extern "C" void kernel_launch(void* const* d_in, const int* in_sizes, int n_in,
                              void* d_out, int out_size) {
    const float* spatial_obs = (const float*)d_in[0];
    const float* card_ctx    = (const float*)d_in[1];
    const float* adj         = (const float*)d_in[2];
    const float* ctx_W  = (const float*)d_in[3];
    const float* ctx_b  = (const float*)d_in[4];
    const float* lnc_s  = (const float*)d_in[5];
    const float* lnc_b  = (const float*)d_in[6];
    const float* in_W   = (const float*)d_in[7];
    const float* in_b   = (const float*)d_in[8];
    const float* lnp_s  = (const float*)d_in[9];
    const float* lnp_b  = (const float*)d_in[10];
    const float* cp_W   = (const float*)d_in[11];
    const float* cp_b   = (const float*)d_in[12];
    const float* Wl     = (const float*)d_in[13];
    const float* Wr     = (const float*)d_in[14];
    const float* Wa     = (const float*)d_in[15];
    const float* op_W   = (const float*)d_in[16];
    const float* op_b   = (const float*)d_in[17];
    const float* card_W = (const float*)d_in[18];
    const float* card_b = (const float*)d_in[19];
    const float* at_W   = (const float*)d_in[20];
    const float* at_b   = (const float*)d_in[21];
    const float* src_W  = (const float*)d_in[22];
    const float* src_b  = (const float*)d_in[23];
    const float* tgt_W  = (const float*)d_in[24];
    const float* tgt_b  = (const float*)d_in[25];
    const float* v1_W   = (const float*)d_in[26];
    const float* v1_b   = (const float*)d_in[27];
    const float* v2_W   = (const float*)d_in[28];
    const float* v2_b   = (const float*)d_in[29];
    float* out = (float*)d_out;

    cudaFuncSetAttribute(attn_kernel, cudaFuncAttributeMaxDynamicSharedMemorySize, ATTN_SMEM);
    cudaFuncSetAttribute(gemm0ln,     cudaFuncAttributeMaxDynamicSharedMemorySize, G0_TOTAL);
    cudaFuncSetAttribute(gemm1_mma,   cudaFuncAttributeMaxDynamicSharedMemorySize, GSM_TOTAL);

    prep_kernel<<<B*NS + 768 + 256, 256>>>(spatial_obs, in_W, in_b,
                                           card_ctx, ctx_W, ctx_b, lnc_s, lnc_b,
                                           cp_W, cp_b, Wl, Wr, op_W);

    dim3 g0(36, 8);
    dim3 g1(36, 4);
    dim3 agrid(B, NS/TI);
    for (int l = 0; l < L; l++) {
        gemm0ln<<<g0, 256, G0_TOTAL>>>(l, lnp_s + l*HD, lnp_b + l*HD);
        attn_kernel<<<agrid, 256, ATTN_SMEM>>>(adj, Wa + l*H*F);
        gemm1_mma<<<g1, 256, GSM_TOTAL>>>(l*768 + 512, op_b + l*HD);
    }

    heads_kernel<<<B, 256>>>(card_W, card_b, at_W, at_b, src_W, src_b,
                             tgt_W, tgt_b, v1_W, v1_b, v2_W, v2_b, out);
}